// round 7
// baseline (speedup 1.0000x reference)
#include <cuda_runtime.h>
#include <cuda_bf16.h>

#define N_NODESC 20000
#define N_EDGESC 320000
#define IN_FC    256
#define OUT_FC   64
#define HEADSC   4
#define ALPHAC   0.1f
#define CAPC     64   // bucket capacity per node (Poisson(16); max ~45)

// ---------------- scratch (static device globals; no allocation) ----------------
// g_ST layout: [dir][node][head][64]; dir0 = S rows (x1@Ws), dir1 = T rows (x2@Wt)
__device__ float g_ST[2 * N_NODESC * HEADSC * OUT_FC];   // ~41 MB
__device__ float g_P1[N_NODESC * 8];   // [node][z]; z<4: S-side, z>=4: T-side (vs a1)
__device__ float g_P2[N_NODESC * 8];   // same vs a2
__device__ int g_degT[N_NODESC], g_degS[N_NODESC];
__device__ int g_nbrT[N_NODESC * CAPC];   // tgt buckets: src nodes
__device__ int g_nbrS[N_NODESC * CAPC];   // src buckets: tgt nodes
// normalized attention weights, bucket-ordered: [node][slot][head]
__device__ float g_WS[N_NODESC * CAPC * HEADSC];   // dir0 (h_st)
__device__ float g_WT[N_NODESC * CAPC * HEADSC];   // dir1 (h_ts)

// ---------------- packed f32x2 helpers ----------------
__device__ __forceinline__ unsigned long long pack2(float a, float b) {
    unsigned long long r;
    asm("mov.b64 %0, {%1, %2};" : "=l"(r) : "f"(a), "f"(b));
    return r;
}
__device__ __forceinline__ void fma2(unsigned long long& d,
                                     unsigned long long a, unsigned long long b) {
    asm("fma.rn.f32x2 %0, %1, %2, %0;" : "+l"(d) : "l"(a), "l"(b));
}
__device__ __forceinline__ float2 unpack2(unsigned long long v) {
    float2 r;
    asm("mov.b64 {%0, %1}, %2;" : "=f"(r.x), "=f"(r.y) : "l"(v));
    return r;
}

// ---------------- kernel 0: zero degree counters ----------------
__global__ void zero_kernel() {
    int i = blockIdx.x * blockDim.x + threadIdx.x;
    if (i < N_NODESC) { g_degT[i] = 0; g_degS[i] = 0; }
}

// ---------------- kernel 1: bucket-CSR fill ----------------
__global__ void fill_kernel(const int* __restrict__ src, const int* __restrict__ tgt) {
    int e = blockIdx.x * blockDim.x + threadIdx.x;
    if (e >= N_EDGESC) return;
    int t = tgt[e], s = src[e];
    int st = atomicAdd(&g_degT[t], 1);
    g_nbrT[(t << 6) + st] = s;
    int ss = atomicAdd(&g_degS[s], 1);
    g_nbrS[(s << 6) + ss] = t;
}

// ---------------- kernel 2: fused 8-way GEMM (M-packed f32x2, dup-B) + projections --
// grid = (ceil(N/128), 8), block 256. Tile 128x64, K-chunk 32, micro 4x8.
// Accumulators pack M-pairs; B stored duplicated in smem so NO pack movs in the
// inner loop: per k = 1 LDS.128 (A) + 4 broadcast LDS.128 (Bdup) + 16 FMA2.
__global__ void __launch_bounds__(256, 3) gemm_kernel(
    const float* __restrict__ x1, const float* __restrict__ x2,
    const float* __restrict__ Ws, const float* __restrict__ Wt,
    const float* __restrict__ a1, const float* __restrict__ a2)
{
    __shared__ float As[32][132];    // [k][m], padded
    __shared__ float BsD[32][128];   // [k][2n]: each B value duplicated
    __shared__ float sA1[64], sA2[64];
    __shared__ float sP1[128], sP2[128];

    int z = blockIdx.y;
    int head = z & 3, dir = z >> 2;
    const float* X = dir ? x2 : x1;
    const float* W = (dir ? Wt : Ws) + head * IN_FC * OUT_FC;
    int m0 = blockIdx.x * 128;
    int tid = threadIdx.x;
    int mg = tid & 31;   // lane: 4 rows mg*4..+3
    int ng = tid >> 5;   // warp: cols ng*8..+7 (broadcast B within warp)

    if (tid < 128) { sP1[tid] = 0.0f; sP2[tid] = 0.0f; }
    if (tid < 64) {
        int aoff = head * 2 * OUT_FC + dir * OUT_FC + tid;
        sA1[tid] = a1[aoff];
        sA2[tid] = a2[aoff];
    }

    unsigned long long acc[2][8];  // [m-pair][col]
#pragma unroll
    for (int i = 0; i < 2; i++)
#pragma unroll
        for (int j = 0; j < 8; j++) acc[i][j] = 0ULL;

    for (int k0 = 0; k0 < IN_FC; k0 += 32) {
        // A tile: 128 rows x 32 k, transposed into As[k][m]
#pragma unroll
        for (int j = 0; j < 4; j++) {
            int i = tid + 256 * j;
            int row = i >> 3;
            int kq = (i & 7) * 4;
            int m = m0 + row;
            float4 v = make_float4(0.f, 0.f, 0.f, 0.f);
            if (m < N_NODESC)
                v = *(const float4*)&X[(size_t)m * IN_FC + k0 + kq];
            As[kq + 0][row] = v.x;
            As[kq + 1][row] = v.y;
            As[kq + 2][row] = v.z;
            As[kq + 3][row] = v.w;
        }
        // B tile: 32 x 64, stored duplicated: BsD[k][2n..2n+1] = B[k][n]
#pragma unroll
        for (int j = 0; j < 2; j++) {
            int i = tid + 256 * j;
            int kr = i >> 4;
            int cq = (i & 15) * 4;
            float4 v = *(const float4*)&W[(size_t)(k0 + kr) * OUT_FC + cq];
            *(float4*)&BsD[kr][cq * 2]     = make_float4(v.x, v.x, v.y, v.y);
            *(float4*)&BsD[kr][cq * 2 + 4] = make_float4(v.z, v.z, v.w, v.w);
        }
        __syncthreads();

#pragma unroll 8
        for (int k = 0; k < 32; k++) {
            ulonglong2 qa = *(const ulonglong2*)&As[k][mg * 4];  // 2 m-pairs
            ulonglong2 b01 = *(const ulonglong2*)&BsD[k][ng * 16];
            ulonglong2 b23 = *(const ulonglong2*)&BsD[k][ng * 16 + 4];
            ulonglong2 b45 = *(const ulonglong2*)&BsD[k][ng * 16 + 8];
            ulonglong2 b67 = *(const ulonglong2*)&BsD[k][ng * 16 + 12];
            fma2(acc[0][0], qa.x, b01.x); fma2(acc[1][0], qa.y, b01.x);
            fma2(acc[0][1], qa.x, b01.y); fma2(acc[1][1], qa.y, b01.y);
            fma2(acc[0][2], qa.x, b23.x); fma2(acc[1][2], qa.y, b23.x);
            fma2(acc[0][3], qa.x, b23.y); fma2(acc[1][3], qa.y, b23.y);
            fma2(acc[0][4], qa.x, b45.x); fma2(acc[1][4], qa.y, b45.x);
            fma2(acc[0][5], qa.x, b45.y); fma2(acc[1][5], qa.y, b45.y);
            fma2(acc[0][6], qa.x, b67.x); fma2(acc[1][6], qa.y, b67.x);
            fma2(acc[0][7], qa.x, b67.y); fma2(acc[1][7], qa.y, b67.y);
        }
        __syncthreads();
    }

    // epilogue: unpack m-pairs -> per-row col vectors; store rows + projections
    float w1v[8], w2v[8];
#pragma unroll
    for (int n = 0; n < 8; n++) {
        w1v[n] = sA1[ng * 8 + n];
        w2v[n] = sA2[ng * 8 + n];
    }
#pragma unroll
    for (int mp = 0; mp < 2; mp++) {
        float lo[8], hi[8];
#pragma unroll
        for (int n = 0; n < 8; n++) {
            float2 f = unpack2(acc[mp][n]);
            lo[n] = f.x; hi[n] = f.y;
        }
#pragma unroll
        for (int half = 0; half < 2; half++) {
            const float* c = half ? hi : lo;
            int r = mg * 4 + mp * 2 + half;
            int m = m0 + r;
            if (m < N_NODESC) {
                float* o = &g_ST[(((size_t)dir * N_NODESC + m) * HEADSC + head) * OUT_FC + ng * 8];
                *(float4*)&o[0] = make_float4(c[0], c[1], c[2], c[3]);
                *(float4*)&o[4] = make_float4(c[4], c[5], c[6], c[7]);
            }
            float d1 = c[0] * w1v[0] + c[1] * w1v[1] + c[2] * w1v[2] + c[3] * w1v[3]
                     + c[4] * w1v[4] + c[5] * w1v[5] + c[6] * w1v[6] + c[7] * w1v[7];
            float d2 = c[0] * w2v[0] + c[1] * w2v[1] + c[2] * w2v[2] + c[3] * w2v[3]
                     + c[4] * w2v[4] + c[5] * w2v[5] + c[6] * w2v[6] + c[7] * w2v[7];
            atomicAdd(&sP1[r], d1);
            atomicAdd(&sP2[r], d2);
        }
    }
    __syncthreads();
    if (tid < 128) {
        int m = m0 + tid;
        if (m < N_NODESC) {
            g_P1[m * 8 + z] = sP1[tid];
            g_P2[m * 8 + z] = sP2[tid];
        }
    }
}

// ---------------- kernel 3: normalized attention weights ----------------
// One warp per (node, dir); lane = (slot 0..7, head 0..3). All 8 chunk iterations
// independent (no breaks) so their loads pipeline; then one shfl-reduce and store.
__global__ void __launch_bounds__(256) weight_kernel() {
    int gw = (blockIdx.x * 256 + threadIdx.x) >> 5;
    int lane = threadIdx.x & 31;
    int node = gw >> 1, dir = gw & 1;
    if (node >= N_NODESC) return;

    int deg;
    const int* __restrict__ nbr;
    const float* __restrict__ P;
    float* __restrict__ Wout;
    int ooff, poff;
    if (dir == 0) {  // h_st: node=src, weights from P2
        deg = g_degS[node]; nbr = g_nbrS + (node << 6);
        P = g_P2; ooff = 0; poff = 4; Wout = g_WS;
    } else {         // h_ts: node=tgt, weights from P1
        deg = g_degT[node]; nbr = g_nbrT + (node << 6);
        P = g_P1; ooff = 4; poff = 0; Wout = g_WT;
    }

    int sh = lane & 3;   // head
    int se = lane >> 2;  // slot within chunk of 8
    float own = __ldg(&P[node * 8 + ooff + sh]);

    float wreg[8];
    float denp = 0.0f;
#pragma unroll
    for (int it = 0; it < 8; it++) {
        int j = it * 8 + se;
        float w = 0.0f;
        if (j < deg) {
            int nb = __ldg(&nbr[j]);
            float e = own + __ldg(&P[nb * 8 + poff + sh]);
            e = fmaxf(e, ALPHAC * e);   // leaky_relu (alpha>0)
            w = __expf(e);
        }
        wreg[it] = w;
        denp += w;
    }
    denp += __shfl_xor_sync(0xFFFFFFFFu, denp, 4);
    denp += __shfl_xor_sync(0xFFFFFFFFu, denp, 8);
    denp += __shfl_xor_sync(0xFFFFFFFFu, denp, 16);
    float inv = (denp > 0.0f) ? (1.0f / denp) : 0.0f;

    float* wb = Wout + ((size_t)node << 8);  // node*CAPC*HEADS
#pragma unroll
    for (int it = 0; it < 8; it++) {
        int j = it * 8 + se;
        if (j < deg) wb[(j << 2) + sh] = wreg[it] * inv;
    }
}

// ---------------- kernel 4: lean gather aggregation + ELU ----------------
// One warp per (node, dir); lane = (head, featgrp) owns 8 contiguous floats.
// Per edge: 2 broadcast LDGs (nbr, alpha) + 2x LDG.128 + 4x fma.f32x2.
__global__ void __launch_bounds__(256) agg_kernel(float* __restrict__ out) {
    int gw = (blockIdx.x * 256 + threadIdx.x) >> 5;
    int lane = threadIdx.x & 31;
    int node = gw >> 1, dir = gw & 1;
    if (node >= N_NODESC) return;

    int deg;
    const int* __restrict__ nbr;
    const float* __restrict__ alph;
    const float* __restrict__ rows;
    if (dir == 0) {  // h_st: gather T rows
        deg = g_degS[node]; nbr = g_nbrS + (node << 6);
        alph = g_WS + ((size_t)node << 8);
        rows = g_ST + (size_t)N_NODESC * (HEADSC * OUT_FC);
    } else {         // h_ts: gather S rows
        deg = g_degT[node]; nbr = g_nbrT + (node << 6);
        alph = g_WT + ((size_t)node << 8);
        rows = g_ST;
    }

    int fh = lane >> 3;
    int laneoff = fh * OUT_FC + (lane & 7) * 8;

    unsigned long long acc[4] = {0ULL, 0ULL, 0ULL, 0ULL};

#pragma unroll 8
    for (int j = 0; j < deg; j++) {
        int nbb = __ldg(&nbr[j]);
        float al = __ldg(&alph[(j << 2) + fh]);
        const float* base = rows + nbb * (HEADSC * OUT_FC) + laneoff;
        ulonglong2 qa = *(const ulonglong2*)(base);
        ulonglong2 qb = *(const ulonglong2*)(base + 4);
        unsigned long long wp = pack2(al, al);
        fma2(acc[0], wp, qa.x);
        fma2(acc[1], wp, qa.y);
        fma2(acc[2], wp, qb.x);
        fma2(acc[3], wp, qb.y);
    }

    float2 f0 = unpack2(acc[0]);
    float2 f1 = unpack2(acc[1]);
    float2 f2 = unpack2(acc[2]);
    float2 f3 = unpack2(acc[3]);
    float r0 = f0.x, r1 = f0.y, r2 = f1.x, r3 = f1.y;
    float r4 = f2.x, r5 = f2.y, r6 = f3.x, r7 = f3.y;
    r0 = (r0 > 0.f) ? r0 : expm1f(r0);
    r1 = (r1 > 0.f) ? r1 : expm1f(r1);
    r2 = (r2 > 0.f) ? r2 : expm1f(r2);
    r3 = (r3 > 0.f) ? r3 : expm1f(r3);
    r4 = (r4 > 0.f) ? r4 : expm1f(r4);
    r5 = (r5 > 0.f) ? r5 : expm1f(r5);
    r6 = (r6 > 0.f) ? r6 : expm1f(r6);
    r7 = (r7 > 0.f) ? r7 : expm1f(r7);

    float* o = out + ((size_t)(dir ? N_NODESC : 0) + node) * (HEADSC * OUT_FC) + laneoff;
    *(float4*)(o)     = make_float4(r0, r1, r2, r3);
    *(float4*)(o + 4) = make_float4(r4, r5, r6, r7);
}

// ---------------- launch ----------------
extern "C" void kernel_launch(void* const* d_in, const int* in_sizes, int n_in,
                              void* d_out, int out_size) {
    const float* x1 = (const float*)d_in[0];
    const float* x2 = (const float*)d_in[1];
    const float* Ws = (const float*)d_in[2];
    const float* Wt = (const float*)d_in[3];
    const float* a1 = (const float*)d_in[4];
    const float* a2 = (const float*)d_in[5];
    const int* tgt  = (const int*)d_in[6];
    const int* src  = (const int*)d_in[7];
    float* out = (float*)d_out;

    zero_kernel<<<(N_NODESC + 255) / 256, 256>>>();
    fill_kernel<<<(N_EDGESC + 255) / 256, 256>>>(src, tgt);

    dim3 gg((N_NODESC + 127) / 128, 8);
    gemm_kernel<<<gg, 256>>>(x1, x2, Ws, Wt, a1, a2);

    weight_kernel<<<(N_NODESC * 2 * 32 + 255) / 256, 256>>>();
    agg_kernel<<<(N_NODESC * 2 * 32 + 255) / 256, 256>>>(out);
}

// round 9
// speedup vs baseline: 1.4134x; 1.4134x over previous
#include <cuda_runtime.h>
#include <cuda_bf16.h>
#include <cstdint>

#define N_NODESC 20000
#define N_EDGESC 320000
#define IN_FC    256
#define OUT_FC   64
#define HEADSC   4
#define ALPHAC   0.1f
#define CAPC     64   // bucket capacity per node (Poisson(16); max ~45)

// ---------------- scratch (static device globals; no allocation) ----------------
// g_ST layout: [dir][node][head][64]; dir0 = S rows (x1@Ws), dir1 = T rows (x2@Wt)
__device__ float g_ST[2 * N_NODESC * HEADSC * OUT_FC];   // ~41 MB
__device__ float g_P1[N_NODESC * 8];   // [node][z]; z = dir*4+head (vs a1)
__device__ float g_P2[N_NODESC * 8];   // same vs a2
__device__ int g_degT[N_NODESC], g_degS[N_NODESC];
__device__ int g_nbrT[N_NODESC * CAPC];
__device__ int g_nbrS[N_NODESC * CAPC];
__device__ float g_WS[N_NODESC * CAPC * HEADSC];   // normalized alpha, dir0
__device__ float g_WT[N_NODESC * CAPC * HEADSC];   // normalized alpha, dir1
// bf16 split operands: X (both dirs) [dir][node][k], W^T per z [z][n][k], hi/lo
__device__ __nv_bfloat16 g_Xh[2 * N_NODESC * IN_FC];
__device__ __nv_bfloat16 g_Xl[2 * N_NODESC * IN_FC];
__device__ __nv_bfloat16 g_Bth[8 * OUT_FC * IN_FC];
__device__ __nv_bfloat16 g_Btl[8 * OUT_FC * IN_FC];

// ---------------- packed f32x2 helpers (agg) ----------------
__device__ __forceinline__ unsigned long long pack2(float a, float b) {
    unsigned long long r;
    asm("mov.b64 %0, {%1, %2};" : "=l"(r) : "f"(a), "f"(b));
    return r;
}
__device__ __forceinline__ void fma2(unsigned long long& d,
                                     unsigned long long a, unsigned long long b) {
    asm("fma.rn.f32x2 %0, %1, %2, %0;" : "+l"(d) : "l"(a), "l"(b));
}
__device__ __forceinline__ float2 unpack2(unsigned long long v) {
    float2 r;
    asm("mov.b64 {%0, %1}, %2;" : "=f"(r.x), "=f"(r.y) : "l"(v));
    return r;
}

// ---------------- mma helpers ----------------
__device__ __forceinline__ uint32_t smem_u32(const void* p) {
    uint32_t a;
    asm("{ .reg .u64 t; cvta.to.shared.u64 t, %1; cvt.u32.u64 %0, t; }" : "=r"(a) : "l"(p));
    return a;
}
// SW64 swizzle for 64-byte rows: conflict-free 8-row x 16B ldmatrix reads
#define SWZ64(o) ((o) ^ (((o) >> 3) & 0x30))

#define LDSM_X4(r, addr) \
    asm volatile("ldmatrix.sync.aligned.m8n8.x4.shared.b16 {%0,%1,%2,%3}, [%4];" \
        : "=r"((r)[0]), "=r"((r)[1]), "=r"((r)[2]), "=r"((r)[3]) : "r"(addr))

#define MMA_BF16(d, a, b0, b1) \
    asm volatile("mma.sync.aligned.m16n8k16.row.col.f32.bf16.bf16.f32 " \
        "{%0,%1,%2,%3},{%4,%5,%6,%7},{%8,%9},{%0,%1,%2,%3};" \
        : "+f"((d)[0]), "+f"((d)[1]), "+f"((d)[2]), "+f"((d)[3]) \
        : "r"((a)[0]), "r"((a)[1]), "r"((a)[2]), "r"((a)[3]), "r"(b0), "r"(b1))

// ---------------- kernel 0: zero degree counters ----------------
__global__ void zero_kernel() {
    int i = blockIdx.x * blockDim.x + threadIdx.x;
    if (i < N_NODESC) { g_degT[i] = 0; g_degS[i] = 0; }
}

// ---------------- kernel 1: bucket-CSR fill ----------------
__global__ void fill_kernel(const int* __restrict__ src, const int* __restrict__ tgt) {
    int e = blockIdx.x * blockDim.x + threadIdx.x;
    if (e >= N_EDGESC) return;
    int t = tgt[e], s = src[e];
    int st = atomicAdd(&g_degT[t], 1);
    g_nbrT[(t << 6) + st] = s;
    int ss = atomicAdd(&g_degS[s], 1);
    g_nbrS[(s << 6) + ss] = t;
}

// ---------------- kernel 2a: convert X (both dirs) to bf16 hi/lo ----------------
__global__ void convx_kernel(const float* __restrict__ x1, const float* __restrict__ x2) {
    int i = blockIdx.x * blockDim.x + threadIdx.x;   // chunk of 8 floats
    const int half = N_NODESC * IN_FC / 8;
    if (i >= 2 * half) return;
    const float* X = (i < half) ? x1 : x2;
    int li = (i < half) ? i : i - half;
    const float4* src = (const float4*)(X + (size_t)li * 8);
    float4 v0 = src[0], v1 = src[1];
    float a[8] = {v0.x, v0.y, v0.z, v0.w, v1.x, v1.y, v1.z, v1.w};
    uint32_t H[4], L[4];
#pragma unroll
    for (int q = 0; q < 4; q++) {
        __nv_bfloat16 h0 = __float2bfloat16(a[2 * q]);
        __nv_bfloat16 h1 = __float2bfloat16(a[2 * q + 1]);
        float r0 = a[2 * q]     - __bfloat162float(h0);
        float r1 = a[2 * q + 1] - __bfloat162float(h1);
        __nv_bfloat16 l0 = __float2bfloat16(r0);
        __nv_bfloat16 l1 = __float2bfloat16(r1);
        H[q] = ((uint32_t)__bfloat16_as_ushort(h1) << 16) | __bfloat16_as_ushort(h0);
        L[q] = ((uint32_t)__bfloat16_as_ushort(l1) << 16) | __bfloat16_as_ushort(l0);
    }
    *(uint4*)(g_Xh + (size_t)i * 8) = make_uint4(H[0], H[1], H[2], H[3]);
    *(uint4*)(g_Xl + (size_t)i * 8) = make_uint4(L[0], L[1], L[2], L[3]);
}

// ---------------- kernel 2b: convert + transpose W to [z][n][k] bf16 hi/lo ------
__global__ void convw_kernel(const float* __restrict__ Ws, const float* __restrict__ Wt) {
    int z = blockIdx.x >> 6;
    int n = blockIdx.x & 63;
    int head = z & 3, dir = z >> 2;
    const float* W = (dir ? Wt : Ws) + head * IN_FC * OUT_FC;
    int k0 = threadIdx.x * 4;
    float a[4];
#pragma unroll
    for (int kk = 0; kk < 4; kk++) a[kk] = __ldg(&W[(size_t)(k0 + kk) * OUT_FC + n]);
    uint32_t H[2], L[2];
#pragma unroll
    for (int q = 0; q < 2; q++) {
        __nv_bfloat16 h0 = __float2bfloat16(a[2 * q]);
        __nv_bfloat16 h1 = __float2bfloat16(a[2 * q + 1]);
        float r0 = a[2 * q]     - __bfloat162float(h0);
        float r1 = a[2 * q + 1] - __bfloat162float(h1);
        __nv_bfloat16 l0 = __float2bfloat16(r0);
        __nv_bfloat16 l1 = __float2bfloat16(r1);
        H[q] = ((uint32_t)__bfloat16_as_ushort(h1) << 16) | __bfloat16_as_ushort(h0);
        L[q] = ((uint32_t)__bfloat16_as_ushort(l1) << 16) | __bfloat16_as_ushort(l0);
    }
    size_t off = ((size_t)z * OUT_FC + n) * IN_FC + k0;
    *(uint2*)(g_Bth + off) = make_uint2(H[0], H[1]);
    *(uint2*)(g_Btl + off) = make_uint2(L[0], L[1]);
}

// ---------------- kernel 3: HMMA bf16x3 GEMM + fused projections ----------------
// grid (157, 8), block 256 = 4 m-warps x 2 n-warps. Tile 128x64, K-chunk 32.
// 3-term split: D = Ah*Bh + Ah*Bl + Al*Bh (~1e-5 rel err).
__global__ void __launch_bounds__(256) gemm_mma_kernel(
    const float* __restrict__ a1, const float* __restrict__ a2)
{
    __shared__ __align__(16) __nv_bfloat16 sAh[128 * 32];  // [m][k], SW64 rows
    __shared__ __align__(16) __nv_bfloat16 sAl[128 * 32];
    __shared__ __align__(16) __nv_bfloat16 sBh[64 * 32];   // [n][k], SW64 rows
    __shared__ __align__(16) __nv_bfloat16 sBl[64 * 32];
    __shared__ float sP1[128], sP2[128];
    __shared__ float sW1[64], sW2[64];

    int z = blockIdx.y, head = z & 3, dir = z >> 2;
    int m0 = blockIdx.x * 128;
    int tid = threadIdx.x, wid = tid >> 5, lane = tid & 31;
    int wm = wid & 3, wn = wid >> 2;

    if (tid < 128) { sP1[tid] = 0.0f; sP2[tid] = 0.0f; }
    if (tid < 64) {
        int ao = head * 2 * OUT_FC + dir * OUT_FC + tid;
        sW1[tid] = a1[ao];
        sW2[tid] = a2[ao];
    }

    uint32_t bAh = smem_u32(sAh), bAl = smem_u32(sAl);
    uint32_t bBh = smem_u32(sBh), bBl = smem_u32(sBl);

    // global load coords
    int arow = tid >> 1, ahalf = tid & 1;          // A: 128 rows x 2 halves (16 k each)
    int am = m0 + arow;
    bool aok = am < N_NODESC;
    int amsafe = aok ? am : 0;
    const __nv_bfloat16* xh = g_Xh + ((size_t)dir * N_NODESC + amsafe) * IN_FC + ahalf * 16;
    const __nv_bfloat16* xl = g_Xl + ((size_t)dir * N_NODESC + amsafe) * IN_FC + ahalf * 16;
    int brow = (tid >> 1) & 63;                    // B: threads 0..127
    const __nv_bfloat16* bh = g_Bth + ((size_t)z * OUT_FC + brow) * IN_FC + ahalf * 16;
    const __nv_bfloat16* bl = g_Btl + ((size_t)z * OUT_FC + brow) * IN_FC + ahalf * 16;

    float acc[2][4][4];
#pragma unroll
    for (int t = 0; t < 2; t++)
#pragma unroll
        for (int na = 0; na < 4; na++)
#pragma unroll
            for (int r = 0; r < 4; r++) acc[t][na][r] = 0.0f;

    for (int c = 0; c < 8; c++) {
        int kc = c * 32;
        // stage A chunk (2 x 16B per thread per buffer)
#pragma unroll
        for (int cg = 0; cg < 2; cg++) {
            uint32_t so = SWZ64((uint32_t)(arow * 64 + ahalf * 32 + cg * 16));
            uint4 hv = make_uint4(0, 0, 0, 0), lv = make_uint4(0, 0, 0, 0);
            if (aok) {
                hv = *(const uint4*)(xh + kc + cg * 8);
                lv = *(const uint4*)(xl + kc + cg * 8);
            }
            *(uint4*)((char*)sAh + so) = hv;
            *(uint4*)((char*)sAl + so) = lv;
        }
        // stage B chunk
        if (tid < 128) {
#pragma unroll
            for (int cg = 0; cg < 2; cg++) {
                uint32_t so = SWZ64((uint32_t)(brow * 64 + ahalf * 32 + cg * 16));
                *(uint4*)((char*)sBh + so) = *(const uint4*)(bh + kc + cg * 8);
                *(uint4*)((char*)sBl + so) = *(const uint4*)(bl + kc + cg * 8);
            }
        }
        __syncthreads();

#pragma unroll
        for (int ks = 0; ks < 2; ks++) {
            int k0 = ks * 16;
            // A fragments: matom t covers rows wm*32 + t*16 .. +15
            uint32_t ah[2][4], al[2][4];
#pragma unroll
            for (int t = 0; t < 2; t++) {
                int rowA = wm * 32 + t * 16 + (lane & 7) + ((lane >> 3) & 1) * 8;
                int kk = k0 + ((lane >> 4) & 1) * 8;
                uint32_t off = SWZ64((uint32_t)(rowA * 64 + kk * 2));
                LDSM_X4(ah[t], bAh + off);
                LDSM_X4(al[t], bAl + off);
            }
            // B fragments: pair p covers n-atoms 2p,2p+1 (16 n)
            uint32_t bhf[2][4], blf[2][4];
#pragma unroll
            for (int p = 0; p < 2; p++) {
                int rowB = wn * 32 + p * 16 + (lane & 7) + ((lane >> 4) & 1) * 8;
                int kk = k0 + ((lane >> 3) & 1) * 8;
                uint32_t off = SWZ64((uint32_t)(rowB * 64 + kk * 2));
                LDSM_X4(bhf[p], bBh + off);
                LDSM_X4(blf[p], bBl + off);
            }
#pragma unroll
            for (int t = 0; t < 2; t++) {
#pragma unroll
                for (int na = 0; na < 4; na++) {
                    int p = na >> 1, s = (na & 1) * 2;
                    MMA_BF16(acc[t][na], ah[t], bhf[p][s], bhf[p][s + 1]);
                    MMA_BF16(acc[t][na], ah[t], blf[p][s], blf[p][s + 1]);
                    MMA_BF16(acc[t][na], al[t], bhf[p][s], bhf[p][s + 1]);
                }
            }
        }
        __syncthreads();
    }

    // epilogue: D fragment -> g_ST + projection partials
    int g = lane >> 2, tig = lane & 3;
#pragma unroll
    for (int t = 0; t < 2; t++) {
#pragma unroll
        for (int half = 0; half < 2; half++) {
            int rl = wm * 32 + t * 16 + g + half * 8;
            int m = m0 + rl;
            if (m >= N_NODESC) continue;
            float* o = &g_ST[(((size_t)dir * N_NODESC + m) * HEADSC + head) * OUT_FC];
            float d1 = 0.f, d2 = 0.f;
#pragma unroll
            for (int na = 0; na < 4; na++) {
                int col = wn * 32 + na * 8 + tig * 2;
                float v0 = acc[t][na][half * 2 + 0];
                float v1 = acc[t][na][half * 2 + 1];
                *(float2*)&o[col] = make_float2(v0, v1);
                d1 += v0 * sW1[col] + v1 * sW1[col + 1];
                d2 += v0 * sW2[col] + v1 * sW2[col + 1];
            }
            atomicAdd(&sP1[rl], d1);
            atomicAdd(&sP2[rl], d2);
        }
    }
    __syncthreads();
    if (tid < 128) {
        int m = m0 + tid;
        if (m < N_NODESC) {
            g_P1[m * 8 + z] = sP1[tid];
            g_P2[m * 8 + z] = sP2[tid];
        }
    }
}

// ---------------- kernel 4: normalized attention weights ----------------
__global__ void __launch_bounds__(256) weight_kernel() {
    int gw = (blockIdx.x * 256 + threadIdx.x) >> 5;
    int lane = threadIdx.x & 31;
    int node = gw >> 1, dir = gw & 1;
    if (node >= N_NODESC) return;

    int deg;
    const int* __restrict__ nbr;
    const float* __restrict__ P;
    float* __restrict__ Wout;
    int ooff, poff;
    if (dir == 0) {
        deg = g_degS[node]; nbr = g_nbrS + (node << 6);
        P = g_P2; ooff = 0; poff = 4; Wout = g_WS;
    } else {
        deg = g_degT[node]; nbr = g_nbrT + (node << 6);
        P = g_P1; ooff = 4; poff = 0; Wout = g_WT;
    }

    int sh = lane & 3;   // head
    int se = lane >> 2;  // slot within chunk of 8
    float own = __ldg(&P[node * 8 + ooff + sh]);

    float wreg[8];
    float denp = 0.0f;
#pragma unroll
    for (int it = 0; it < 8; it++) {
        int j = it * 8 + se;
        float w = 0.0f;
        if (j < deg) {
            int nb = __ldg(&nbr[j]);
            float e = own + __ldg(&P[nb * 8 + poff + sh]);
            e = fmaxf(e, ALPHAC * e);
            w = __expf(e);
        }
        wreg[it] = w;
        denp += w;
    }
    denp += __shfl_xor_sync(0xFFFFFFFFu, denp, 4);
    denp += __shfl_xor_sync(0xFFFFFFFFu, denp, 8);
    denp += __shfl_xor_sync(0xFFFFFFFFu, denp, 16);
    float inv = (denp > 0.0f) ? (1.0f / denp) : 0.0f;

    float* wb = Wout + ((size_t)node << 8);
#pragma unroll
    for (int it = 0; it < 8; it++) {
        int j = it * 8 + se;
        if (j < deg) wb[(j << 2) + sh] = wreg[it] * inv;
    }
}

// ---------------- kernel 5: lean gather aggregation + ELU ----------------
__global__ void __launch_bounds__(256) agg_kernel(float* __restrict__ out) {
    int gw = (blockIdx.x * 256 + threadIdx.x) >> 5;
    int lane = threadIdx.x & 31;
    int node = gw >> 1, dir = gw & 1;
    if (node >= N_NODESC) return;

    int deg;
    const int* __restrict__ nbr;
    const float* __restrict__ alph;
    const float* __restrict__ rows;
    if (dir == 0) {
        deg = g_degS[node]; nbr = g_nbrS + (node << 6);
        alph = g_WS + ((size_t)node << 8);
        rows = g_ST + (size_t)N_NODESC * (HEADSC * OUT_FC);
    } else {
        deg = g_degT[node]; nbr = g_nbrT + (node << 6);
        alph = g_WT + ((size_t)node << 8);
        rows = g_ST;
    }

    int fh = lane >> 3;
    int laneoff = fh * OUT_FC + (lane & 7) * 8;

    unsigned long long acc[4] = {0ULL, 0ULL, 0ULL, 0ULL};

#pragma unroll 8
    for (int j = 0; j < deg; j++) {
        int nbb = __ldg(&nbr[j]);
        float al = __ldg(&alph[(j << 2) + fh]);
        const float* base = rows + nbb * (HEADSC * OUT_FC) + laneoff;
        ulonglong2 qa = *(const ulonglong2*)(base);
        ulonglong2 qb = *(const ulonglong2*)(base + 4);
        unsigned long long wp = pack2(al, al);
        fma2(acc[0], wp, qa.x);
        fma2(acc[1], wp, qa.y);
        fma2(acc[2], wp, qb.x);
        fma2(acc[3], wp, qb.y);
    }

    float2 f0 = unpack2(acc[0]);
    float2 f1 = unpack2(acc[1]);
    float2 f2 = unpack2(acc[2]);
    float2 f3 = unpack2(acc[3]);
    float r0 = f0.x, r1 = f0.y, r2 = f1.x, r3 = f1.y;
    float r4 = f2.x, r5 = f2.y, r6 = f3.x, r7 = f3.y;
    r0 = (r0 > 0.f) ? r0 : expm1f(r0);
    r1 = (r1 > 0.f) ? r1 : expm1f(r1);
    r2 = (r2 > 0.f) ? r2 : expm1f(r2);
    r3 = (r3 > 0.f) ? r3 : expm1f(r3);
    r4 = (r4 > 0.f) ? r4 : expm1f(r4);
    r5 = (r5 > 0.f) ? r5 : expm1f(r5);
    r6 = (r6 > 0.f) ? r6 : expm1f(r6);
    r7 = (r7 > 0.f) ? r7 : expm1f(r7);

    float* o = out + ((size_t)(dir ? N_NODESC : 0) + node) * (HEADSC * OUT_FC) + laneoff;
    *(float4*)(o)     = make_float4(r0, r1, r2, r3);
    *(float4*)(o + 4) = make_float4(r4, r5, r6, r7);
}

// ---------------- launch ----------------
extern "C" void kernel_launch(void* const* d_in, const int* in_sizes, int n_in,
                              void* d_out, int out_size) {
    const float* x1 = (const float*)d_in[0];
    const float* x2 = (const float*)d_in[1];
    const float* Ws = (const float*)d_in[2];
    const float* Wt = (const float*)d_in[3];
    const float* a1 = (const float*)d_in[4];
    const float* a2 = (const float*)d_in[5];
    const int* tgt  = (const int*)d_in[6];
    const int* src  = (const int*)d_in[7];
    float* out = (float*)d_out;

    zero_kernel<<<(N_NODESC + 255) / 256, 256>>>();
    fill_kernel<<<(N_EDGESC + 255) / 256, 256>>>(src, tgt);

    convx_kernel<<<(2 * N_NODESC * IN_FC / 8 + 255) / 256, 256>>>(x1, x2);
    convw_kernel<<<8 * OUT_FC, IN_FC / 4>>>(Ws, Wt);

    dim3 gg((N_NODESC + 127) / 128, 8);
    gemm_mma_kernel<<<gg, 256>>>(a1, a2);

    weight_kernel<<<(N_NODESC * 2 * 32 + 255) / 256, 256>>>();
    agg_kernel<<<(N_NODESC * 2 * 32 + 255) / 256, 256>>>(out);
}

// round 10
// speedup vs baseline: 1.5197x; 1.0752x over previous
#include <cuda_runtime.h>
#include <cuda_bf16.h>
#include <cuda_fp16.h>
#include <cstdint>

#define N_NODESC 20000
#define N_EDGESC 320000
#define IN_FC    256
#define OUT_FC   64
#define HEADSC   4
#define ALPHAC   0.1f
#define CAPC     64   // bucket capacity per node (Poisson(16); max ~45)

// ---------------- scratch (static device globals; no allocation) ----------------
// g_STh layout: [dir][node][head][64] fp16; dir0 = S rows (x1@Ws), dir1 = T rows (x2@Wt)
__device__ __half g_STh[2 * N_NODESC * HEADSC * OUT_FC];   // ~20.5 MB
__device__ float g_P1[N_NODESC * 8];   // [node][z]; z = dir*4+head (vs a1)
__device__ float g_P2[N_NODESC * 8];   // same vs a2
__device__ int g_degT[N_NODESC], g_degS[N_NODESC];
__device__ int g_nbrT[N_NODESC * CAPC];
__device__ int g_nbrS[N_NODESC * CAPC];
__device__ float g_WS[N_NODESC * CAPC * HEADSC];   // normalized alpha, dir0
__device__ float g_WT[N_NODESC * CAPC * HEADSC];   // normalized alpha, dir1
// bf16 split operands: X (both dirs) [dir][node][k], W^T per z [z][n][k], hi/lo
__device__ __nv_bfloat16 g_Xh[2 * N_NODESC * IN_FC];
__device__ __nv_bfloat16 g_Xl[2 * N_NODESC * IN_FC];
__device__ __nv_bfloat16 g_Bth[8 * OUT_FC * IN_FC];
__device__ __nv_bfloat16 g_Btl[8 * OUT_FC * IN_FC];

// ---------------- mma helpers ----------------
__device__ __forceinline__ uint32_t smem_u32(const void* p) {
    uint32_t a;
    asm("{ .reg .u64 t; cvta.to.shared.u64 t, %1; cvt.u32.u64 %0, t; }" : "=r"(a) : "l"(p));
    return a;
}
// SW64 swizzle for 64-byte rows: conflict-free 8-row x 16B ldmatrix reads
#define SWZ64(o) ((o) ^ (((o) >> 3) & 0x30))

#define LDSM_X4(r, addr) \
    asm volatile("ldmatrix.sync.aligned.m8n8.x4.shared.b16 {%0,%1,%2,%3}, [%4];" \
        : "=r"((r)[0]), "=r"((r)[1]), "=r"((r)[2]), "=r"((r)[3]) : "r"(addr))

#define MMA_BF16(d, a, b0, b1) \
    asm volatile("mma.sync.aligned.m16n8k16.row.col.f32.bf16.bf16.f32 " \
        "{%0,%1,%2,%3},{%4,%5,%6,%7},{%8,%9},{%0,%1,%2,%3};" \
        : "+f"((d)[0]), "+f"((d)[1]), "+f"((d)[2]), "+f"((d)[3]) \
        : "r"((a)[0]), "r"((a)[1]), "r"((a)[2]), "r"((a)[3]), "r"(b0), "r"(b1))

// ---------------- kernel 0: zero degree counters ----------------
__global__ void zero_kernel() {
    int i = blockIdx.x * blockDim.x + threadIdx.x;
    if (i < N_NODESC) { g_degT[i] = 0; g_degS[i] = 0; }
}

// ---------------- kernel 1: bucket-CSR fill ----------------
__global__ void fill_kernel(const int* __restrict__ src, const int* __restrict__ tgt) {
    int e = blockIdx.x * blockDim.x + threadIdx.x;
    if (e >= N_EDGESC) return;
    int t = tgt[e], s = src[e];
    int st = atomicAdd(&g_degT[t], 1);
    g_nbrT[(t << 6) + st] = s;
    int ss = atomicAdd(&g_degS[s], 1);
    g_nbrS[(s << 6) + ss] = t;
}

// ---------------- kernel 2a: convert X (both dirs) to bf16 hi/lo ----------------
__global__ void convx_kernel(const float* __restrict__ x1, const float* __restrict__ x2) {
    int i = blockIdx.x * blockDim.x + threadIdx.x;   // chunk of 8 floats
    const int half = N_NODESC * IN_FC / 8;
    if (i >= 2 * half) return;
    const float* X = (i < half) ? x1 : x2;
    int li = (i < half) ? i : i - half;
    const float4* src = (const float4*)(X + (size_t)li * 8);
    float4 v0 = src[0], v1 = src[1];
    float a[8] = {v0.x, v0.y, v0.z, v0.w, v1.x, v1.y, v1.z, v1.w};
    uint32_t H[4], L[4];
#pragma unroll
    for (int q = 0; q < 4; q++) {
        __nv_bfloat16 h0 = __float2bfloat16(a[2 * q]);
        __nv_bfloat16 h1 = __float2bfloat16(a[2 * q + 1]);
        float r0 = a[2 * q]     - __bfloat162float(h0);
        float r1 = a[2 * q + 1] - __bfloat162float(h1);
        __nv_bfloat16 l0 = __float2bfloat16(r0);
        __nv_bfloat16 l1 = __float2bfloat16(r1);
        H[q] = ((uint32_t)__bfloat16_as_ushort(h1) << 16) | __bfloat16_as_ushort(h0);
        L[q] = ((uint32_t)__bfloat16_as_ushort(l1) << 16) | __bfloat16_as_ushort(l0);
    }
    *(uint4*)(g_Xh + (size_t)i * 8) = make_uint4(H[0], H[1], H[2], H[3]);
    *(uint4*)(g_Xl + (size_t)i * 8) = make_uint4(L[0], L[1], L[2], L[3]);
}

// ---------------- kernel 2b: convert + transpose W to [z][n][k] bf16 hi/lo ------
__global__ void convw_kernel(const float* __restrict__ Ws, const float* __restrict__ Wt) {
    int z = blockIdx.x >> 6;
    int n = blockIdx.x & 63;
    int head = z & 3, dir = z >> 2;
    const float* W = (dir ? Wt : Ws) + head * IN_FC * OUT_FC;
    int k0 = threadIdx.x * 4;
    float a[4];
#pragma unroll
    for (int kk = 0; kk < 4; kk++) a[kk] = __ldg(&W[(size_t)(k0 + kk) * OUT_FC + n]);
    uint32_t H[2], L[2];
#pragma unroll
    for (int q = 0; q < 2; q++) {
        __nv_bfloat16 h0 = __float2bfloat16(a[2 * q]);
        __nv_bfloat16 h1 = __float2bfloat16(a[2 * q + 1]);
        float r0 = a[2 * q]     - __bfloat162float(h0);
        float r1 = a[2 * q + 1] - __bfloat162float(h1);
        __nv_bfloat16 l0 = __float2bfloat16(r0);
        __nv_bfloat16 l1 = __float2bfloat16(r1);
        H[q] = ((uint32_t)__bfloat16_as_ushort(h1) << 16) | __bfloat16_as_ushort(h0);
        L[q] = ((uint32_t)__bfloat16_as_ushort(l1) << 16) | __bfloat16_as_ushort(l0);
    }
    size_t off = ((size_t)z * OUT_FC + n) * IN_FC + k0;
    *(uint2*)(g_Bth + off) = make_uint2(H[0], H[1]);
    *(uint2*)(g_Btl + off) = make_uint2(L[0], L[1]);
}

// ---------------- kernel 3: HMMA bf16x3 GEMM + fused projections, fp16 rows out --
// grid (157, 8), block 256 = 4 m-warps x 2 n-warps. Tile 128x64, K-chunk 32.
// 3-term split: D = Ah*Bh + Ah*Bl + Al*Bh (~1e-5 rel err). Rows stored fp16.
__global__ void __launch_bounds__(256) gemm_mma_kernel(
    const float* __restrict__ a1, const float* __restrict__ a2)
{
    __shared__ __align__(16) __nv_bfloat16 sAh[128 * 32];  // [m][k], SW64 rows
    __shared__ __align__(16) __nv_bfloat16 sAl[128 * 32];
    __shared__ __align__(16) __nv_bfloat16 sBh[64 * 32];   // [n][k], SW64 rows
    __shared__ __align__(16) __nv_bfloat16 sBl[64 * 32];
    __shared__ float sP1[128], sP2[128];
    __shared__ float sW1[64], sW2[64];

    int z = blockIdx.y, head = z & 3, dir = z >> 2;
    int m0 = blockIdx.x * 128;
    int tid = threadIdx.x, wid = tid >> 5, lane = tid & 31;
    int wm = wid & 3, wn = wid >> 2;

    if (tid < 128) { sP1[tid] = 0.0f; sP2[tid] = 0.0f; }
    if (tid < 64) {
        int ao = head * 2 * OUT_FC + dir * OUT_FC + tid;
        sW1[tid] = a1[ao];
        sW2[tid] = a2[ao];
    }

    uint32_t bAh = smem_u32(sAh), bAl = smem_u32(sAl);
    uint32_t bBh = smem_u32(sBh), bBl = smem_u32(sBl);

    // global load coords
    int arow = tid >> 1, ahalf = tid & 1;          // A: 128 rows x 2 halves (16 k each)
    int am = m0 + arow;
    bool aok = am < N_NODESC;
    int amsafe = aok ? am : 0;
    const __nv_bfloat16* xh = g_Xh + ((size_t)dir * N_NODESC + amsafe) * IN_FC + ahalf * 16;
    const __nv_bfloat16* xl = g_Xl + ((size_t)dir * N_NODESC + amsafe) * IN_FC + ahalf * 16;
    int brow = (tid >> 1) & 63;                    // B: threads 0..127
    const __nv_bfloat16* bh = g_Bth + ((size_t)z * OUT_FC + brow) * IN_FC + ahalf * 16;
    const __nv_bfloat16* bl = g_Btl + ((size_t)z * OUT_FC + brow) * IN_FC + ahalf * 16;

    float acc[2][4][4];
#pragma unroll
    for (int t = 0; t < 2; t++)
#pragma unroll
        for (int na = 0; na < 4; na++)
#pragma unroll
            for (int r = 0; r < 4; r++) acc[t][na][r] = 0.0f;

    for (int c = 0; c < 8; c++) {
        int kc = c * 32;
        // stage A chunk (2 x 16B per thread per buffer)
#pragma unroll
        for (int cg = 0; cg < 2; cg++) {
            uint32_t so = SWZ64((uint32_t)(arow * 64 + ahalf * 32 + cg * 16));
            uint4 hv = make_uint4(0, 0, 0, 0), lv = make_uint4(0, 0, 0, 0);
            if (aok) {
                hv = *(const uint4*)(xh + kc + cg * 8);
                lv = *(const uint4*)(xl + kc + cg * 8);
            }
            *(uint4*)((char*)sAh + so) = hv;
            *(uint4*)((char*)sAl + so) = lv;
        }
        // stage B chunk
        if (tid < 128) {
#pragma unroll
            for (int cg = 0; cg < 2; cg++) {
                uint32_t so = SWZ64((uint32_t)(brow * 64 + ahalf * 32 + cg * 16));
                *(uint4*)((char*)sBh + so) = *(const uint4*)(bh + kc + cg * 8);
                *(uint4*)((char*)sBl + so) = *(const uint4*)(bl + kc + cg * 8);
            }
        }
        __syncthreads();

#pragma unroll
        for (int ks = 0; ks < 2; ks++) {
            int k0 = ks * 16;
            uint32_t ah[2][4], al[2][4];
#pragma unroll
            for (int t = 0; t < 2; t++) {
                int rowA = wm * 32 + t * 16 + (lane & 7) + ((lane >> 3) & 1) * 8;
                int kk = k0 + ((lane >> 4) & 1) * 8;
                uint32_t off = SWZ64((uint32_t)(rowA * 64 + kk * 2));
                LDSM_X4(ah[t], bAh + off);
                LDSM_X4(al[t], bAl + off);
            }
            uint32_t bhf[2][4], blf[2][4];
#pragma unroll
            for (int p = 0; p < 2; p++) {
                int rowB = wn * 32 + p * 16 + (lane & 7) + ((lane >> 4) & 1) * 8;
                int kk = k0 + ((lane >> 3) & 1) * 8;
                uint32_t off = SWZ64((uint32_t)(rowB * 64 + kk * 2));
                LDSM_X4(bhf[p], bBh + off);
                LDSM_X4(blf[p], bBl + off);
            }
#pragma unroll
            for (int t = 0; t < 2; t++) {
#pragma unroll
                for (int na = 0; na < 4; na++) {
                    int p = na >> 1, s = (na & 1) * 2;
                    MMA_BF16(acc[t][na], ah[t], bhf[p][s], bhf[p][s + 1]);
                    MMA_BF16(acc[t][na], ah[t], blf[p][s], blf[p][s + 1]);
                    MMA_BF16(acc[t][na], al[t], bhf[p][s], bhf[p][s + 1]);
                }
            }
        }
        __syncthreads();
    }

    // epilogue: D fragment -> fp16 rows + projection partials
    int g = lane >> 2, tig = lane & 3;
#pragma unroll
    for (int t = 0; t < 2; t++) {
#pragma unroll
        for (int half = 0; half < 2; half++) {
            int rl = wm * 32 + t * 16 + g + half * 8;
            int m = m0 + rl;
            if (m >= N_NODESC) continue;
            __half* o = &g_STh[(((size_t)dir * N_NODESC + m) * HEADSC + head) * OUT_FC];
            float d1 = 0.f, d2 = 0.f;
#pragma unroll
            for (int na = 0; na < 4; na++) {
                int col = wn * 32 + na * 8 + tig * 2;
                float v0 = acc[t][na][half * 2 + 0];
                float v1 = acc[t][na][half * 2 + 1];
                *(__half2*)&o[col] = __floats2half2_rn(v0, v1);
                d1 += v0 * sW1[col] + v1 * sW1[col + 1];
                d2 += v0 * sW2[col] + v1 * sW2[col + 1];
            }
            atomicAdd(&sP1[rl], d1);
            atomicAdd(&sP2[rl], d2);
        }
    }
    __syncthreads();
    if (tid < 128) {
        int m = m0 + tid;
        if (m < N_NODESC) {
            g_P1[m * 8 + z] = sP1[tid];
            g_P2[m * 8 + z] = sP2[tid];
        }
    }
}

// ---------------- kernel 4: normalized attention weights ----------------
__global__ void __launch_bounds__(256) weight_kernel() {
    int gw = (blockIdx.x * 256 + threadIdx.x) >> 5;
    int lane = threadIdx.x & 31;
    int node = gw >> 1, dir = gw & 1;
    if (node >= N_NODESC) return;

    int deg;
    const int* __restrict__ nbr;
    const float* __restrict__ P;
    float* __restrict__ Wout;
    int ooff, poff;
    if (dir == 0) {
        deg = g_degS[node]; nbr = g_nbrS + (node << 6);
        P = g_P2; ooff = 0; poff = 4; Wout = g_WS;
    } else {
        deg = g_degT[node]; nbr = g_nbrT + (node << 6);
        P = g_P1; ooff = 4; poff = 0; Wout = g_WT;
    }

    int sh = lane & 3;   // head
    int se = lane >> 2;  // slot within chunk of 8
    float own = __ldg(&P[node * 8 + ooff + sh]);

    float wreg[8];
    float denp = 0.0f;
#pragma unroll
    for (int it = 0; it < 8; it++) {
        int j = it * 8 + se;
        float w = 0.0f;
        if (j < deg) {
            int nb = __ldg(&nbr[j]);
            float e = own + __ldg(&P[nb * 8 + poff + sh]);
            e = fmaxf(e, ALPHAC * e);
            w = __expf(e);
        }
        wreg[it] = w;
        denp += w;
    }
    denp += __shfl_xor_sync(0xFFFFFFFFu, denp, 4);
    denp += __shfl_xor_sync(0xFFFFFFFFu, denp, 8);
    denp += __shfl_xor_sync(0xFFFFFFFFu, denp, 16);
    float inv = (denp > 0.0f) ? (1.0f / denp) : 0.0f;

    float* wb = Wout + ((size_t)node << 8);
#pragma unroll
    for (int it = 0; it < 8; it++) {
        int j = it * 8 + se;
        if (j < deg) wb[(j << 2) + sh] = wreg[it] * inv;
    }
}

// ---------------- kernel 5: lean gather aggregation (fp16 rows) + ELU ----------------
// One warp per (node, dir); lane = (head, featgrp) owns 8 contiguous features.
// Per edge per lane: nbr + alpha broadcast LDGs + 1x LDG.128 (8 fp16) + cvt + 8 FFMA.
__global__ void __launch_bounds__(256) agg_kernel(float* __restrict__ out) {
    int gw = (blockIdx.x * 256 + threadIdx.x) >> 5;
    int lane = threadIdx.x & 31;
    int node = gw >> 1, dir = gw & 1;
    if (node >= N_NODESC) return;

    int deg;
    const int* __restrict__ nbr;
    const float* __restrict__ alph;
    const __half* __restrict__ rows;
    if (dir == 0) {
        deg = g_degS[node]; nbr = g_nbrS + (node << 6);
        alph = g_WS + ((size_t)node << 8);
        rows = g_STh + (size_t)N_NODESC * (HEADSC * OUT_FC);
    } else {
        deg = g_degT[node]; nbr = g_nbrT + (node << 6);
        alph = g_WT + ((size_t)node << 8);
        rows = g_STh;
    }

    int fh = lane >> 3;
    int laneoff = fh * OUT_FC + (lane & 7) * 8;

    float a0 = 0.f, a1v = 0.f, a2v = 0.f, a3 = 0.f;
    float a4 = 0.f, a5 = 0.f, a6 = 0.f, a7 = 0.f;

#pragma unroll 8
    for (int j = 0; j < deg; j++) {
        int nbb = __ldg(&nbr[j]);
        float al = __ldg(&alph[(j << 2) + fh]);
        const __half* base = rows + nbb * (HEADSC * OUT_FC) + laneoff;
        uint4 q = *(const uint4*)(base);
        float2 v0 = __half22float2(*(const __half2*)&q.x);
        float2 v1 = __half22float2(*(const __half2*)&q.y);
        float2 v2 = __half22float2(*(const __half2*)&q.z);
        float2 v3 = __half22float2(*(const __half2*)&q.w);
        a0 += al * v0.x; a1v += al * v0.y;
        a2v += al * v1.x; a3 += al * v1.y;
        a4 += al * v2.x; a5 += al * v2.y;
        a6 += al * v3.x; a7 += al * v3.y;
    }

    float r0 = (a0 > 0.f) ? a0 : expm1f(a0);
    float r1 = (a1v > 0.f) ? a1v : expm1f(a1v);
    float r2 = (a2v > 0.f) ? a2v : expm1f(a2v);
    float r3 = (a3 > 0.f) ? a3 : expm1f(a3);
    float r4 = (a4 > 0.f) ? a4 : expm1f(a4);
    float r5 = (a5 > 0.f) ? a5 : expm1f(a5);
    float r6 = (a6 > 0.f) ? a6 : expm1f(a6);
    float r7 = (a7 > 0.f) ? a7 : expm1f(a7);

    float* o = out + ((size_t)(dir ? N_NODESC : 0) + node) * (HEADSC * OUT_FC) + laneoff;
    *(float4*)(o)     = make_float4(r0, r1, r2, r3);
    *(float4*)(o + 4) = make_float4(r4, r5, r6, r7);
}

// ---------------- launch ----------------
extern "C" void kernel_launch(void* const* d_in, const int* in_sizes, int n_in,
                              void* d_out, int out_size) {
    const float* x1 = (const float*)d_in[0];
    const float* x2 = (const float*)d_in[1];
    const float* Ws = (const float*)d_in[2];
    const float* Wt = (const float*)d_in[3];
    const float* a1 = (const float*)d_in[4];
    const float* a2 = (const float*)d_in[5];
    const int* tgt  = (const int*)d_in[6];
    const int* src  = (const int*)d_in[7];
    float* out = (float*)d_out;

    zero_kernel<<<(N_NODESC + 255) / 256, 256>>>();
    fill_kernel<<<(N_EDGESC + 255) / 256, 256>>>(src, tgt);

    convx_kernel<<<(2 * N_NODESC * IN_FC / 8 + 255) / 256, 256>>>(x1, x2);
    convw_kernel<<<8 * OUT_FC, IN_FC / 4>>>(Ws, Wt);

    dim3 gg((N_NODESC + 127) / 128, 8);
    gemm_mma_kernel<<<gg, 256>>>(a1, a2);

    weight_kernel<<<(N_NODESC * 2 * 32 + 255) / 256, 256>>>();
    agg_kernel<<<(N_NODESC * 2 * 32 + 255) / 256, 256>>>(out);
}

// round 11
// speedup vs baseline: 1.8592x; 1.2234x over previous
#include <cuda_runtime.h>
#include <cuda_bf16.h>
#include <cuda_fp16.h>
#include <cstdint>

#define N_NODESC 20000
#define N_EDGESC 320000
#define IN_FC    256
#define OUT_FC   64
#define HEADSC   4
#define ALPHAC   0.1f
#define CAPC     64   // bucket capacity per node (Poisson(16); max ~45)

// ---------------- scratch (static device globals; no allocation) ----------------
// g_STh layout: [dir][node][head][64] fp16
__device__ __half g_STh[2 * N_NODESC * HEADSC * OUT_FC];   // ~20.5 MB
__device__ float g_P1[N_NODESC * 8];   // [node][z]; z = dir*4+head (vs a1)
__device__ float g_P2[N_NODESC * 8];   // same vs a2
__device__ int g_degT[N_NODESC], g_degS[N_NODESC];
__device__ int g_nbrT[N_NODESC * CAPC];
__device__ int g_nbrS[N_NODESC * CAPC];
__device__ float g_WS[N_NODESC * CAPC * HEADSC];   // normalized alpha, dir0
__device__ float g_WT[N_NODESC * CAPC * HEADSC];   // normalized alpha, dir1
// fp16 operands: X (both dirs) [dir][node][k], W^T per z [z][n][k]
__device__ __half g_Xf[2 * N_NODESC * IN_FC];
__device__ __half g_Btf[8 * OUT_FC * IN_FC];

// ---------------- mma helpers ----------------
__device__ __forceinline__ uint32_t smem_u32(const void* p) {
    uint32_t a;
    asm("{ .reg .u64 t; cvta.to.shared.u64 t, %1; cvt.u32.u64 %0, t; }" : "=r"(a) : "l"(p));
    return a;
}
// SW64 swizzle for 64-byte rows: conflict-free 8-row x 16B ldmatrix reads
#define SWZ64(o) ((o) ^ (((o) >> 3) & 0x30))

#define LDSM_X4(r, addr) \
    asm volatile("ldmatrix.sync.aligned.m8n8.x4.shared.b16 {%0,%1,%2,%3}, [%4];" \
        : "=r"((r)[0]), "=r"((r)[1]), "=r"((r)[2]), "=r"((r)[3]) : "r"(addr))

#define MMA_F16(d, a, b0, b1) \
    asm volatile("mma.sync.aligned.m16n8k16.row.col.f32.f16.f16.f32 " \
        "{%0,%1,%2,%3},{%4,%5,%6,%7},{%8,%9},{%0,%1,%2,%3};" \
        : "+f"((d)[0]), "+f"((d)[1]), "+f"((d)[2]), "+f"((d)[3]) \
        : "r"((a)[0]), "r"((a)[1]), "r"((a)[2]), "r"((a)[3]), "r"(b0), "r"(b1))

// ---------------- kernel 0: zero degree counters ----------------
__global__ void zero_kernel() {
    int i = blockIdx.x * blockDim.x + threadIdx.x;
    if (i < N_NODESC) { g_degT[i] = 0; g_degS[i] = 0; }
}

// ---------------- kernel 1: bucket-CSR fill ----------------
__global__ void fill_kernel(const int* __restrict__ src, const int* __restrict__ tgt) {
    int e = blockIdx.x * blockDim.x + threadIdx.x;
    if (e >= N_EDGESC) return;
    int t = tgt[e], s = src[e];
    int st = atomicAdd(&g_degT[t], 1);
    g_nbrT[(t << 6) + st] = s;
    int ss = atomicAdd(&g_degS[s], 1);
    g_nbrS[(s << 6) + ss] = t;
}

// ---------------- kernel 2a: convert X (both dirs) to fp16 ----------------
__global__ void convx_kernel(const float* __restrict__ x1, const float* __restrict__ x2) {
    int i = blockIdx.x * blockDim.x + threadIdx.x;   // chunk of 8 floats
    const int half = N_NODESC * IN_FC / 8;
    if (i >= 2 * half) return;
    const float* X = (i < half) ? x1 : x2;
    int li = (i < half) ? i : i - half;
    const float4* src = (const float4*)(X + (size_t)li * 8);
    float4 v0 = src[0], v1 = src[1];
    __half2 h0 = __floats2half2_rn(v0.x, v0.y);
    __half2 h1 = __floats2half2_rn(v0.z, v0.w);
    __half2 h2 = __floats2half2_rn(v1.x, v1.y);
    __half2 h3 = __floats2half2_rn(v1.z, v1.w);
    uint4 o;
    o.x = *(uint32_t*)&h0; o.y = *(uint32_t*)&h1;
    o.z = *(uint32_t*)&h2; o.w = *(uint32_t*)&h3;
    *(uint4*)(g_Xf + (size_t)i * 8) = o;
}

// ---------------- kernel 2b: convert + transpose W to [z][n][k] fp16 ------
__global__ void convw_kernel(const float* __restrict__ Ws, const float* __restrict__ Wt) {
    int z = blockIdx.x >> 6;
    int n = blockIdx.x & 63;
    int head = z & 3, dir = z >> 2;
    const float* W = (dir ? Wt : Ws) + head * IN_FC * OUT_FC;
    int k0 = threadIdx.x * 4;
    float a[4];
#pragma unroll
    for (int kk = 0; kk < 4; kk++) a[kk] = __ldg(&W[(size_t)(k0 + kk) * OUT_FC + n]);
    __half2 h0 = __floats2half2_rn(a[0], a[1]);
    __half2 h1 = __floats2half2_rn(a[2], a[3]);
    uint2 o;
    o.x = *(uint32_t*)&h0; o.y = *(uint32_t*)&h1;
    *(uint2*)(g_Btf + ((size_t)z * OUT_FC + n) * IN_FC + k0) = o;
}

// ---------------- kernel 3: HMMA fp16 GEMM + fused projections, fp16 rows out ----
// grid (157, 8), block 256 = 4 m-warps x 2 n-warps. Tile 128x64, K-chunk 32.
__global__ void __launch_bounds__(256) gemm_mma_kernel(
    const float* __restrict__ a1, const float* __restrict__ a2)
{
    __shared__ __align__(16) __half sA[128 * 32];  // [m][k], SW64 rows
    __shared__ __align__(16) __half sB[64 * 32];   // [n][k], SW64 rows
    __shared__ float sP1[128], sP2[128];
    __shared__ float sW1[64], sW2[64];

    int z = blockIdx.y, head = z & 3, dir = z >> 2;
    int m0 = blockIdx.x * 128;
    int tid = threadIdx.x, wid = tid >> 5, lane = tid & 31;
    int wm = wid & 3, wn = wid >> 2;

    if (tid < 128) { sP1[tid] = 0.0f; sP2[tid] = 0.0f; }
    if (tid < 64) {
        int ao = head * 2 * OUT_FC + dir * OUT_FC + tid;
        sW1[tid] = a1[ao];
        sW2[tid] = a2[ao];
    }

    uint32_t bA = smem_u32(sA), bB = smem_u32(sB);

    // global load coords
    int arow = tid >> 1, ahalf = tid & 1;          // A: 128 rows x 2 halves (16 k each)
    int am = m0 + arow;
    bool aok = am < N_NODESC;
    int amsafe = aok ? am : 0;
    const __half* xf = g_Xf + ((size_t)dir * N_NODESC + amsafe) * IN_FC + ahalf * 16;
    int brow = (tid >> 1) & 63;                    // B: threads 0..127
    const __half* bf = g_Btf + ((size_t)z * OUT_FC + brow) * IN_FC + ahalf * 16;

    float acc[2][4][4];
#pragma unroll
    for (int t = 0; t < 2; t++)
#pragma unroll
        for (int na = 0; na < 4; na++)
#pragma unroll
            for (int r = 0; r < 4; r++) acc[t][na][r] = 0.0f;

    for (int c = 0; c < 8; c++) {
        int kc = c * 32;
        // stage A chunk (2 x 16B per thread)
#pragma unroll
        for (int cg = 0; cg < 2; cg++) {
            uint32_t so = SWZ64((uint32_t)(arow * 64 + ahalf * 32 + cg * 16));
            uint4 v = make_uint4(0, 0, 0, 0);
            if (aok) v = *(const uint4*)(xf + kc + cg * 8);
            *(uint4*)((char*)sA + so) = v;
        }
        // stage B chunk
        if (tid < 128) {
#pragma unroll
            for (int cg = 0; cg < 2; cg++) {
                uint32_t so = SWZ64((uint32_t)(brow * 64 + ahalf * 32 + cg * 16));
                *(uint4*)((char*)sB + so) = *(const uint4*)(bf + kc + cg * 8);
            }
        }
        __syncthreads();

#pragma unroll
        for (int ks = 0; ks < 2; ks++) {
            int k0 = ks * 16;
            uint32_t af[2][4];
#pragma unroll
            for (int t = 0; t < 2; t++) {
                int rowA = wm * 32 + t * 16 + (lane & 7) + ((lane >> 3) & 1) * 8;
                int kk = k0 + ((lane >> 4) & 1) * 8;
                uint32_t off = SWZ64((uint32_t)(rowA * 64 + kk * 2));
                LDSM_X4(af[t], bA + off);
            }
            uint32_t bfr[2][4];
#pragma unroll
            for (int p = 0; p < 2; p++) {
                int rowB = wn * 32 + p * 16 + (lane & 7) + ((lane >> 4) & 1) * 8;
                int kk = k0 + ((lane >> 3) & 1) * 8;
                uint32_t off = SWZ64((uint32_t)(rowB * 64 + kk * 2));
                LDSM_X4(bfr[p], bB + off);
            }
#pragma unroll
            for (int t = 0; t < 2; t++) {
#pragma unroll
                for (int na = 0; na < 4; na++) {
                    int p = na >> 1, s = (na & 1) * 2;
                    MMA_F16(acc[t][na], af[t], bfr[p][s], bfr[p][s + 1]);
                }
            }
        }
        __syncthreads();
    }

    // epilogue: D fragment -> fp16 rows + projection partials
    int g = lane >> 2, tig = lane & 3;
#pragma unroll
    for (int t = 0; t < 2; t++) {
#pragma unroll
        for (int half = 0; half < 2; half++) {
            int rl = wm * 32 + t * 16 + g + half * 8;
            int m = m0 + rl;
            if (m >= N_NODESC) continue;
            __half* o = &g_STh[(((size_t)dir * N_NODESC + m) * HEADSC + head) * OUT_FC];
            float d1 = 0.f, d2 = 0.f;
#pragma unroll
            for (int na = 0; na < 4; na++) {
                int col = wn * 32 + na * 8 + tig * 2;
                float v0 = acc[t][na][half * 2 + 0];
                float v1 = acc[t][na][half * 2 + 1];
                *(__half2*)&o[col] = __floats2half2_rn(v0, v1);
                d1 += v0 * sW1[col] + v1 * sW1[col + 1];
                d2 += v0 * sW2[col] + v1 * sW2[col + 1];
            }
            atomicAdd(&sP1[rl], d1);
            atomicAdd(&sP2[rl], d2);
        }
    }
    __syncthreads();
    if (tid < 128) {
        int m = m0 + tid;
        if (m < N_NODESC) {
            g_P1[m * 8 + z] = sP1[tid];
            g_P2[m * 8 + z] = sP2[tid];
        }
    }
}

// ---------------- kernel 4: normalized attention weights ----------------
__global__ void __launch_bounds__(256) weight_kernel() {
    int gw = (blockIdx.x * 256 + threadIdx.x) >> 5;
    int lane = threadIdx.x & 31;
    int node = gw >> 1, dir = gw & 1;
    if (node >= N_NODESC) return;

    int deg;
    const int* __restrict__ nbr;
    const float* __restrict__ P;
    float* __restrict__ Wout;
    int ooff, poff;
    if (dir == 0) {
        deg = g_degS[node]; nbr = g_nbrS + (node << 6);
        P = g_P2; ooff = 0; poff = 4; Wout = g_WS;
    } else {
        deg = g_degT[node]; nbr = g_nbrT + (node << 6);
        P = g_P1; ooff = 4; poff = 0; Wout = g_WT;
    }

    int sh = lane & 3;   // head
    int se = lane >> 2;  // slot within chunk of 8
    float own = __ldg(&P[node * 8 + ooff + sh]);

    float wreg[8];
    float denp = 0.0f;
#pragma unroll
    for (int it = 0; it < 8; it++) {
        int j = it * 8 + se;
        float w = 0.0f;
        if (j < deg) {
            int nb = __ldg(&nbr[j]);
            float e = own + __ldg(&P[nb * 8 + poff + sh]);
            e = fmaxf(e, ALPHAC * e);
            w = __expf(e);
        }
        wreg[it] = w;
        denp += w;
    }
    denp += __shfl_xor_sync(0xFFFFFFFFu, denp, 4);
    denp += __shfl_xor_sync(0xFFFFFFFFu, denp, 8);
    denp += __shfl_xor_sync(0xFFFFFFFFu, denp, 16);
    float inv = (denp > 0.0f) ? (1.0f / denp) : 0.0f;

    float* wb = Wout + ((size_t)node << 8);
#pragma unroll
    for (int it = 0; it < 8; it++) {
        int j = it * 8 + se;
        if (j < deg) wb[(j << 2) + sh] = wreg[it] * inv;
    }
}

// ---------------- kernel 5: lean gather aggregation (fp16 rows) + ELU ----------------
__global__ void __launch_bounds__(256) agg_kernel(float* __restrict__ out) {
    int gw = (blockIdx.x * 256 + threadIdx.x) >> 5;
    int lane = threadIdx.x & 31;
    int node = gw >> 1, dir = gw & 1;
    if (node >= N_NODESC) return;

    int deg;
    const int* __restrict__ nbr;
    const float* __restrict__ alph;
    const __half* __restrict__ rows;
    if (dir == 0) {
        deg = g_degS[node]; nbr = g_nbrS + (node << 6);
        alph = g_WS + ((size_t)node << 8);
        rows = g_STh + (size_t)N_NODESC * (HEADSC * OUT_FC);
    } else {
        deg = g_degT[node]; nbr = g_nbrT + (node << 6);
        alph = g_WT + ((size_t)node << 8);
        rows = g_STh;
    }

    int fh = lane >> 3;
    int laneoff = fh * OUT_FC + (lane & 7) * 8;

    float a0 = 0.f, a1v = 0.f, a2v = 0.f, a3 = 0.f;
    float a4 = 0.f, a5 = 0.f, a6 = 0.f, a7 = 0.f;

#pragma unroll 8
    for (int j = 0; j < deg; j++) {
        int nbb = __ldg(&nbr[j]);
        float al = __ldg(&alph[(j << 2) + fh]);
        const __half* base = rows + nbb * (HEADSC * OUT_FC) + laneoff;
        uint4 q = *(const uint4*)(base);
        float2 v0 = __half22float2(*(const __half2*)&q.x);
        float2 v1 = __half22float2(*(const __half2*)&q.y);
        float2 v2 = __half22float2(*(const __half2*)&q.z);
        float2 v3 = __half22float2(*(const __half2*)&q.w);
        a0 += al * v0.x; a1v += al * v0.y;
        a2v += al * v1.x; a3 += al * v1.y;
        a4 += al * v2.x; a5 += al * v2.y;
        a6 += al * v3.x; a7 += al * v3.y;
    }

    float r0 = (a0 > 0.f) ? a0 : expm1f(a0);
    float r1 = (a1v > 0.f) ? a1v : expm1f(a1v);
    float r2 = (a2v > 0.f) ? a2v : expm1f(a2v);
    float r3 = (a3 > 0.f) ? a3 : expm1f(a3);
    float r4 = (a4 > 0.f) ? a4 : expm1f(a4);
    float r5 = (a5 > 0.f) ? a5 : expm1f(a5);
    float r6 = (a6 > 0.f) ? a6 : expm1f(a6);
    float r7 = (a7 > 0.f) ? a7 : expm1f(a7);

    float* o = out + ((size_t)(dir ? N_NODESC : 0) + node) * (HEADSC * OUT_FC) + laneoff;
    *(float4*)(o)     = make_float4(r0, r1, r2, r3);
    *(float4*)(o + 4) = make_float4(r4, r5, r6, r7);
}

// ---------------- launch ----------------
extern "C" void kernel_launch(void* const* d_in, const int* in_sizes, int n_in,
                              void* d_out, int out_size) {
    const float* x1 = (const float*)d_in[0];
    const float* x2 = (const float*)d_in[1];
    const float* Ws = (const float*)d_in[2];
    const float* Wt = (const float*)d_in[3];
    const float* a1 = (const float*)d_in[4];
    const float* a2 = (const float*)d_in[5];
    const int* tgt  = (const int*)d_in[6];
    const int* src  = (const int*)d_in[7];
    float* out = (float*)d_out;

    // side stream + events for capture-legal fork/join (created on the first,
    // uncaptured, correctness call; reused thereafter — resources, not work)
    static cudaStream_t s2 = nullptr;
    static cudaEvent_t evFork = nullptr, evJoin = nullptr;
    if (s2 == nullptr) {
        cudaStreamCreateWithFlags(&s2, cudaStreamNonBlocking);
        cudaEventCreateWithFlags(&evFork, cudaEventDisableTiming);
        cudaEventCreateWithFlags(&evJoin, cudaEventDisableTiming);
    }

    // fork: CSR chain (zero -> fill) runs concurrently with conv + gemm
    cudaEventRecord(evFork, 0);
    cudaStreamWaitEvent(s2, evFork, 0);
    zero_kernel<<<(N_NODESC + 255) / 256, 256, 0, s2>>>();
    fill_kernel<<<(N_EDGESC + 255) / 256, 256, 0, s2>>>(src, tgt);
    cudaEventRecord(evJoin, s2);

    convx_kernel<<<(2 * N_NODESC * IN_FC / 8 + 255) / 256, 256>>>(x1, x2);
    convw_kernel<<<8 * OUT_FC, IN_FC / 4>>>(Ws, Wt);

    dim3 gg((N_NODESC + 127) / 128, 8);
    gemm_mma_kernel<<<gg, 256>>>(a1, a2);

    // join: weight needs both the CSR and the projections
    cudaStreamWaitEvent(0, evJoin, 0);
    weight_kernel<<<(N_NODESC * 2 * 32 + 255) / 256, 256>>>();
    agg_kernel<<<(N_NODESC * 2 * 32 + 255) / 256, 256>>>(out);
}

// round 12
// speedup vs baseline: 2.0003x; 1.0759x over previous
#include <cuda_runtime.h>
#include <cuda_bf16.h>
#include <cuda_fp16.h>
#include <cstdint>

#define N_NODESC 20000
#define N_EDGESC 320000
#define IN_FC    256
#define OUT_FC   64
#define HEADSC   4
#define ALPHAC   0.1f
#define CAPC     64   // bucket capacity per node (Poisson(16); max ~45)

// ---------------- scratch (static device globals; no allocation) ----------------
// g_STh layout: [dir][node][head][64] fp16
__device__ __half g_STh[2 * N_NODESC * HEADSC * OUT_FC];   // ~20.5 MB
__device__ float g_P1[N_NODESC * 8];   // [node][z]; z = dir*4+head (vs a1)
__device__ float g_P2[N_NODESC * 8];   // same vs a2
__device__ int g_degT[N_NODESC], g_degS[N_NODESC];
__device__ int g_nbrT[N_NODESC * CAPC];
__device__ int g_nbrS[N_NODESC * CAPC];
// fp16 operands: X (both dirs) [dir][node][k], W^T per z [z][n][k]
__device__ __half g_Xf[2 * N_NODESC * IN_FC];
__device__ __half g_Btf[8 * OUT_FC * IN_FC];

// ---------------- mma helpers ----------------
__device__ __forceinline__ uint32_t smem_u32(const void* p) {
    uint32_t a;
    asm("{ .reg .u64 t; cvta.to.shared.u64 t, %1; cvt.u32.u64 %0, t; }" : "=r"(a) : "l"(p));
    return a;
}
// SW64 swizzle for 64-byte rows: conflict-free 8-row x 16B ldmatrix reads
#define SWZ64(o) ((o) ^ (((o) >> 3) & 0x30))

#define LDSM_X4(r, addr) \
    asm volatile("ldmatrix.sync.aligned.m8n8.x4.shared.b16 {%0,%1,%2,%3}, [%4];" \
        : "=r"((r)[0]), "=r"((r)[1]), "=r"((r)[2]), "=r"((r)[3]) : "r"(addr))

#define MMA_F16(d, a, b0, b1) \
    asm volatile("mma.sync.aligned.m16n8k16.row.col.f32.f16.f16.f32 " \
        "{%0,%1,%2,%3},{%4,%5,%6,%7},{%8,%9},{%0,%1,%2,%3};" \
        : "+f"((d)[0]), "+f"((d)[1]), "+f"((d)[2]), "+f"((d)[3]) \
        : "r"((a)[0]), "r"((a)[1]), "r"((a)[2]), "r"((a)[3]), "r"(b0), "r"(b1))

// ---------------- kernel 0: zero degree counters ----------------
__global__ void zero_kernel() {
    int i = blockIdx.x * blockDim.x + threadIdx.x;
    if (i < N_NODESC) { g_degT[i] = 0; g_degS[i] = 0; }
}

// ---------------- kernel 1: bucket-CSR fill ----------------
__global__ void fill_kernel(const int* __restrict__ src, const int* __restrict__ tgt) {
    int e = blockIdx.x * blockDim.x + threadIdx.x;
    if (e >= N_EDGESC) return;
    int t = tgt[e], s = src[e];
    int st = atomicAdd(&g_degT[t], 1);
    g_nbrT[(t << 6) + st] = s;
    int ss = atomicAdd(&g_degS[s], 1);
    g_nbrS[(s << 6) + ss] = t;
}

// ---------------- kernel 2: fused fp16 conversion (X + transposed W) ----------------
__global__ void conv_kernel(const float* __restrict__ x1, const float* __restrict__ x2,
                            const float* __restrict__ Ws, const float* __restrict__ Wt) {
    const int NX = 2 * N_NODESC * IN_FC / 8;           // X groups of 8 floats
    const int NW = 8 * OUT_FC * IN_FC / 4;             // W groups of 4 floats
    int i = blockIdx.x * blockDim.x + threadIdx.x;
    if (i < NX) {
        const int half = NX / 2;
        const float* X = (i < half) ? x1 : x2;
        int li = (i < half) ? i : i - half;
        const float4* src = (const float4*)(X + (size_t)li * 8);
        float4 v0 = src[0], v1 = src[1];
        __half2 h0 = __floats2half2_rn(v0.x, v0.y);
        __half2 h1 = __floats2half2_rn(v0.z, v0.w);
        __half2 h2 = __floats2half2_rn(v1.x, v1.y);
        __half2 h3 = __floats2half2_rn(v1.z, v1.w);
        uint4 o;
        o.x = *(uint32_t*)&h0; o.y = *(uint32_t*)&h1;
        o.z = *(uint32_t*)&h2; o.w = *(uint32_t*)&h3;
        *(uint4*)(g_Xf + (size_t)i * 8) = o;
    } else {
        int k = i - NX;
        if (k >= NW) return;
        int k0 = (k & 63) * 4;     // 64 k-groups per (z, n)
        int zn = k >> 6;
        int z = zn >> 6, n = zn & 63;
        int head = z & 3, dir = z >> 2;
        const float* W = (dir ? Wt : Ws) + head * IN_FC * OUT_FC;
        float a[4];
#pragma unroll
        for (int kk = 0; kk < 4; kk++) a[kk] = __ldg(&W[(size_t)(k0 + kk) * OUT_FC + n]);
        __half2 h0 = __floats2half2_rn(a[0], a[1]);
        __half2 h1 = __floats2half2_rn(a[2], a[3]);
        uint2 o;
        o.x = *(uint32_t*)&h0; o.y = *(uint32_t*)&h1;
        *(uint2*)(g_Btf + ((size_t)z * OUT_FC + n) * IN_FC + k0) = o;
    }
}

// ---------------- kernel 3: HMMA fp16 GEMM + fused projections, fp16 rows out ----
// grid (157, 8), block 256 = 4 m-warps x 2 n-warps. Tile 128x64, K-chunk 32.
__global__ void __launch_bounds__(256) gemm_mma_kernel(
    const float* __restrict__ a1, const float* __restrict__ a2)
{
    __shared__ __align__(16) __half sA[128 * 32];  // [m][k], SW64 rows
    __shared__ __align__(16) __half sB[64 * 32];   // [n][k], SW64 rows
    __shared__ float sP1[128], sP2[128];
    __shared__ float sW1[64], sW2[64];

    int z = blockIdx.y, head = z & 3, dir = z >> 2;
    int m0 = blockIdx.x * 128;
    int tid = threadIdx.x, wid = tid >> 5, lane = tid & 31;
    int wm = wid & 3, wn = wid >> 2;

    if (tid < 128) { sP1[tid] = 0.0f; sP2[tid] = 0.0f; }
    if (tid < 64) {
        int ao = head * 2 * OUT_FC + dir * OUT_FC + tid;
        sW1[tid] = a1[ao];
        sW2[tid] = a2[ao];
    }

    uint32_t bA = smem_u32(sA), bB = smem_u32(sB);

    int arow = tid >> 1, ahalf = tid & 1;
    int am = m0 + arow;
    bool aok = am < N_NODESC;
    int amsafe = aok ? am : 0;
    const __half* xf = g_Xf + ((size_t)dir * N_NODESC + amsafe) * IN_FC + ahalf * 16;
    int brow = (tid >> 1) & 63;
    const __half* bf = g_Btf + ((size_t)z * OUT_FC + brow) * IN_FC + ahalf * 16;

    float acc[2][4][4];
#pragma unroll
    for (int t = 0; t < 2; t++)
#pragma unroll
        for (int na = 0; na < 4; na++)
#pragma unroll
            for (int r = 0; r < 4; r++) acc[t][na][r] = 0.0f;

    for (int c = 0; c < 8; c++) {
        int kc = c * 32;
#pragma unroll
        for (int cg = 0; cg < 2; cg++) {
            uint32_t so = SWZ64((uint32_t)(arow * 64 + ahalf * 32 + cg * 16));
            uint4 v = make_uint4(0, 0, 0, 0);
            if (aok) v = *(const uint4*)(xf + kc + cg * 8);
            *(uint4*)((char*)sA + so) = v;
        }
        if (tid < 128) {
#pragma unroll
            for (int cg = 0; cg < 2; cg++) {
                uint32_t so = SWZ64((uint32_t)(brow * 64 + ahalf * 32 + cg * 16));
                *(uint4*)((char*)sB + so) = *(const uint4*)(bf + kc + cg * 8);
            }
        }
        __syncthreads();

#pragma unroll
        for (int ks = 0; ks < 2; ks++) {
            int k0 = ks * 16;
            uint32_t af[2][4];
#pragma unroll
            for (int t = 0; t < 2; t++) {
                int rowA = wm * 32 + t * 16 + (lane & 7) + ((lane >> 3) & 1) * 8;
                int kk = k0 + ((lane >> 4) & 1) * 8;
                uint32_t off = SWZ64((uint32_t)(rowA * 64 + kk * 2));
                LDSM_X4(af[t], bA + off);
            }
            uint32_t bfr[2][4];
#pragma unroll
            for (int p = 0; p < 2; p++) {
                int rowB = wn * 32 + p * 16 + (lane & 7) + ((lane >> 4) & 1) * 8;
                int kk = k0 + ((lane >> 3) & 1) * 8;
                uint32_t off = SWZ64((uint32_t)(rowB * 64 + kk * 2));
                LDSM_X4(bfr[p], bB + off);
            }
#pragma unroll
            for (int t = 0; t < 2; t++) {
#pragma unroll
                for (int na = 0; na < 4; na++) {
                    int p = na >> 1, s = (na & 1) * 2;
                    MMA_F16(acc[t][na], af[t], bfr[p][s], bfr[p][s + 1]);
                }
            }
        }
        __syncthreads();
    }

    // epilogue: D fragment -> fp16 rows + projection partials
    int g = lane >> 2, tig = lane & 3;
#pragma unroll
    for (int t = 0; t < 2; t++) {
#pragma unroll
        for (int half = 0; half < 2; half++) {
            int rl = wm * 32 + t * 16 + g + half * 8;
            int m = m0 + rl;
            if (m >= N_NODESC) continue;
            __half* o = &g_STh[(((size_t)dir * N_NODESC + m) * HEADSC + head) * OUT_FC];
            float d1 = 0.f, d2 = 0.f;
#pragma unroll
            for (int na = 0; na < 4; na++) {
                int col = wn * 32 + na * 8 + tig * 2;
                float v0 = acc[t][na][half * 2 + 0];
                float v1 = acc[t][na][half * 2 + 1];
                *(__half2*)&o[col] = __floats2half2_rn(v0, v1);
                d1 += v0 * sW1[col] + v1 * sW1[col + 1];
                d2 += v0 * sW2[col] + v1 * sW2[col + 1];
            }
            atomicAdd(&sP1[rl], d1);
            atomicAdd(&sP2[rl], d2);
        }
    }
    __syncthreads();
    if (tid < 128) {
        int m = m0 + tid;
        if (m < N_NODESC) {
            g_P1[m * 8 + z] = sP1[tid];
            g_P2[m * 8 + z] = sP2[tid];
        }
    }
}

// ---------------- kernel 4: fused softmax-weight + gather aggregation + ELU ------
// One warp per (node, dir).
// Phase 1 (lane = slot*4+head): compute normalized alphas, stage in smem.
// Phase 2 (lane = head*8+featgrp): per edge, LDS alpha (broadcast, feeds FFMA
// only — never an address) + LDG nbr + LDG.128 row + cvt + 8 FFMA.
__global__ void __launch_bounds__(256) agg_kernel(float* __restrict__ out) {
    __shared__ float sAl[8][CAPC * HEADSC];   // per-warp alpha tile: [slot][head]

    int wslot = threadIdx.x >> 5;
    int gw = (blockIdx.x * 256 + threadIdx.x) >> 5;
    int lane = threadIdx.x & 31;
    int node = gw >> 1, dir = gw & 1;
    if (node >= N_NODESC) return;

    int deg;
    const int* __restrict__ nbr;
    const float* __restrict__ P;
    const __half* __restrict__ rows;
    int ooff, poff;
    if (dir == 0) {  // h_st: node=src, weights from P2, gather T rows
        deg = g_degS[node]; nbr = g_nbrS + (node << 6);
        P = g_P2; ooff = 0; poff = 4;
        rows = g_STh + (size_t)N_NODESC * (HEADSC * OUT_FC);
    } else {         // h_ts: node=tgt, weights from P1, gather S rows
        deg = g_degT[node]; nbr = g_nbrT + (node << 6);
        P = g_P1; ooff = 4; poff = 0;
        rows = g_STh;
    }

    // ---- phase 1: alphas ----
    int sh = lane & 3;   // head
    int se = lane >> 2;  // slot within chunk of 8
    float own = __ldg(&P[node * 8 + ooff + sh]);

    float wreg[8];
    float denp = 0.0f;
#pragma unroll
    for (int it = 0; it < 8; it++) {
        int j = it * 8 + se;
        float w = 0.0f;
        if (j < deg) {
            int nb = __ldg(&nbr[j]);
            float e = own + __ldg(&P[nb * 8 + poff + sh]);
            e = fmaxf(e, ALPHAC * e);   // leaky_relu (alpha>0)
            w = __expf(e);
        }
        wreg[it] = w;
        denp += w;
    }
    denp += __shfl_xor_sync(0xFFFFFFFFu, denp, 4);
    denp += __shfl_xor_sync(0xFFFFFFFFu, denp, 8);
    denp += __shfl_xor_sync(0xFFFFFFFFu, denp, 16);
    float inv = (denp > 0.0f) ? (1.0f / denp) : 0.0f;
#pragma unroll
    for (int it = 0; it < 8; it++)
        sAl[wslot][((it * 8 + se) << 2) + sh] = wreg[it] * inv;
    __syncwarp();

    // ---- phase 2: gather + accumulate ----
    int fh = lane >> 3;
    int laneoff = fh * OUT_FC + (lane & 7) * 8;

    float a0 = 0.f, a1v = 0.f, a2v = 0.f, a3 = 0.f;
    float a4 = 0.f, a5 = 0.f, a6 = 0.f, a7 = 0.f;

#pragma unroll 8
    for (int j = 0; j < deg; j++) {
        int nbb = __ldg(&nbr[j]);
        float al = sAl[wslot][(j << 2) + fh];
        const __half* base = rows + nbb * (HEADSC * OUT_FC) + laneoff;
        uint4 q = *(const uint4*)(base);
        float2 v0 = __half22float2(*(const __half2*)&q.x);
        float2 v1 = __half22float2(*(const __half2*)&q.y);
        float2 v2 = __half22float2(*(const __half2*)&q.z);
        float2 v3 = __half22float2(*(const __half2*)&q.w);
        a0 += al * v0.x; a1v += al * v0.y;
        a2v += al * v1.x; a3 += al * v1.y;
        a4 += al * v2.x; a5 += al * v2.y;
        a6 += al * v3.x; a7 += al * v3.y;
    }

    float r0 = (a0 > 0.f) ? a0 : expm1f(a0);
    float r1 = (a1v > 0.f) ? a1v : expm1f(a1v);
    float r2 = (a2v > 0.f) ? a2v : expm1f(a2v);
    float r3 = (a3 > 0.f) ? a3 : expm1f(a3);
    float r4 = (a4 > 0.f) ? a4 : expm1f(a4);
    float r5 = (a5 > 0.f) ? a5 : expm1f(a5);
    float r6 = (a6 > 0.f) ? a6 : expm1f(a6);
    float r7 = (a7 > 0.f) ? a7 : expm1f(a7);

    float* o = out + ((size_t)(dir ? N_NODESC : 0) + node) * (HEADSC * OUT_FC) + laneoff;
    *(float4*)(o)     = make_float4(r0, r1, r2, r3);
    *(float4*)(o + 4) = make_float4(r4, r5, r6, r7);
}

// ---------------- launch ----------------
extern "C" void kernel_launch(void* const* d_in, const int* in_sizes, int n_in,
                              void* d_out, int out_size) {
    const float* x1 = (const float*)d_in[0];
    const float* x2 = (const float*)d_in[1];
    const float* Ws = (const float*)d_in[2];
    const float* Wt = (const float*)d_in[3];
    const float* a1 = (const float*)d_in[4];
    const float* a2 = (const float*)d_in[5];
    const int* tgt  = (const int*)d_in[6];
    const int* src  = (const int*)d_in[7];
    float* out = (float*)d_out;

    // side stream + events for capture-legal fork/join (created on the first,
    // uncaptured, correctness call; reused thereafter — resources, not work)
    static cudaStream_t s2 = nullptr;
    static cudaEvent_t evFork = nullptr, evJoin = nullptr;
    if (s2 == nullptr) {
        cudaStreamCreateWithFlags(&s2, cudaStreamNonBlocking);
        cudaEventCreateWithFlags(&evFork, cudaEventDisableTiming);
        cudaEventCreateWithFlags(&evJoin, cudaEventDisableTiming);
    }

    // fork: CSR chain (zero -> fill) runs concurrently with conv + gemm
    cudaEventRecord(evFork, 0);
    cudaStreamWaitEvent(s2, evFork, 0);
    zero_kernel<<<(N_NODESC + 255) / 256, 256, 0, s2>>>();
    fill_kernel<<<(N_EDGESC + 255) / 256, 256, 0, s2>>>(src, tgt);
    cudaEventRecord(evJoin, s2);

    const int NCONV = 2 * N_NODESC * IN_FC / 8 + 8 * OUT_FC * IN_FC / 4;
    conv_kernel<<<(NCONV + 255) / 256, 256>>>(x1, x2, Ws, Wt);

    dim3 gg((N_NODESC + 127) / 128, 8);
    gemm_mma_kernel<<<gg, 256>>>(a1, a2);

    // join: agg needs both the CSR and the projections/rows
    cudaStreamWaitEvent(0, evJoin, 0);
    agg_kernel<<<(N_NODESC * 2 * 32 + 255) / 256, 256>>>(out);
}

// round 13
// speedup vs baseline: 2.2817x; 1.1407x over previous
#include <cuda_runtime.h>
#include <cuda_bf16.h>
#include <cuda_fp16.h>
#include <cstdint>

#define N_NODESC 20000
#define N_EDGESC 320000
#define IN_FC    256
#define OUT_FC   64
#define HEADSC   4
#define ALPHAC   0.1f
#define CAPC     64   // bucket capacity per node (Poisson(16); max ~45)

// ---------------- scratch (static device globals; no allocation) ----------------
// g_STh layout: [dir][node][head][64] fp16
__device__ __half g_STh[2 * N_NODESC * HEADSC * OUT_FC];   // ~20.5 MB
__device__ float g_P1[N_NODESC * 8];   // [node][z]; z = dir*4+head (vs a1)
__device__ float g_P2[N_NODESC * 8];   // same vs a2
__device__ int g_degT[N_NODESC], g_degS[N_NODESC];
__device__ int g_nbrT[N_NODESC * CAPC];
__device__ int g_nbrS[N_NODESC * CAPC];
// fp16 operands: X (both dirs) [dir][node][k], W^T per z [z][n][k]
__device__ __half g_Xf[2 * N_NODESC * IN_FC];
__device__ __half g_Btf[8 * OUT_FC * IN_FC];

// ---------------- mma helpers ----------------
__device__ __forceinline__ uint32_t smem_u32(const void* p) {
    uint32_t a;
    asm("{ .reg .u64 t; cvta.to.shared.u64 t, %1; cvt.u32.u64 %0, t; }" : "=r"(a) : "l"(p));
    return a;
}
// SW64 swizzle for 64-byte rows: conflict-free 8-row x 16B ldmatrix reads
#define SWZ64(o) ((o) ^ (((o) >> 3) & 0x30))

#define LDSM_X4(r, addr) \
    asm volatile("ldmatrix.sync.aligned.m8n8.x4.shared.b16 {%0,%1,%2,%3}, [%4];" \
        : "=r"((r)[0]), "=r"((r)[1]), "=r"((r)[2]), "=r"((r)[3]) : "r"(addr))

#define MMA_F16(d, a, b0, b1) \
    asm volatile("mma.sync.aligned.m16n8k16.row.col.f32.f16.f16.f32 " \
        "{%0,%1,%2,%3},{%4,%5,%6,%7},{%8,%9},{%0,%1,%2,%3};" \
        : "+f"((d)[0]), "+f"((d)[1]), "+f"((d)[2]), "+f"((d)[3]) \
        : "r"((a)[0]), "r"((a)[1]), "r"((a)[2]), "r"((a)[3]), "r"(b0), "r"(b1))

#define CP_ASYNC_16(dst, src, zf) \
    asm volatile("cp.async.cg.shared.global [%0], [%1], 16, %2;" \
        :: "r"(dst), "l"(src), "r"(zf))
#define CP_COMMIT() asm volatile("cp.async.commit_group;")
#define CP_WAIT1()  asm volatile("cp.async.wait_group 1;")
#define CP_WAIT0()  asm volatile("cp.async.wait_group 0;")

// ---------------- kernel 0: zero degree counters ----------------
__global__ void zero_kernel() {
    int i = blockIdx.x * blockDim.x + threadIdx.x;
    if (i < N_NODESC) { g_degT[i] = 0; g_degS[i] = 0; }
}

// ---------------- kernel 1: bucket-CSR fill ----------------
__global__ void fill_kernel(const int* __restrict__ src, const int* __restrict__ tgt) {
    int e = blockIdx.x * blockDim.x + threadIdx.x;
    if (e >= N_EDGESC) return;
    int t = tgt[e], s = src[e];
    int st = atomicAdd(&g_degT[t], 1);
    g_nbrT[(t << 6) + st] = s;
    int ss = atomicAdd(&g_degS[s], 1);
    g_nbrS[(s << 6) + ss] = t;
}

// ---------------- kernel 2: fused fp16 conversion (X + transposed W) ----------------
__global__ void conv_kernel(const float* __restrict__ x1, const float* __restrict__ x2,
                            const float* __restrict__ Ws, const float* __restrict__ Wt) {
    const int NX = 2 * N_NODESC * IN_FC / 8;           // X groups of 8 floats
    const int NW = 8 * OUT_FC * IN_FC / 4;             // W groups of 4 floats
    int i = blockIdx.x * blockDim.x + threadIdx.x;
    if (i < NX) {
        const int half = NX / 2;
        const float* X = (i < half) ? x1 : x2;
        int li = (i < half) ? i : i - half;
        const float4* src = (const float4*)(X + (size_t)li * 8);
        float4 v0 = src[0], v1 = src[1];
        __half2 h0 = __floats2half2_rn(v0.x, v0.y);
        __half2 h1 = __floats2half2_rn(v0.z, v0.w);
        __half2 h2 = __floats2half2_rn(v1.x, v1.y);
        __half2 h3 = __floats2half2_rn(v1.z, v1.w);
        uint4 o;
        o.x = *(uint32_t*)&h0; o.y = *(uint32_t*)&h1;
        o.z = *(uint32_t*)&h2; o.w = *(uint32_t*)&h3;
        *(uint4*)(g_Xf + (size_t)i * 8) = o;
    } else {
        int k = i - NX;
        if (k >= NW) return;
        int k0 = (k & 63) * 4;     // 64 k-groups per (z, n)
        int zn = k >> 6;
        int z = zn >> 6, n = zn & 63;
        int head = z & 3, dir = z >> 2;
        const float* W = (dir ? Wt : Ws) + head * IN_FC * OUT_FC;
        float a[4];
#pragma unroll
        for (int kk = 0; kk < 4; kk++) a[kk] = __ldg(&W[(size_t)(k0 + kk) * OUT_FC + n]);
        __half2 h0 = __floats2half2_rn(a[0], a[1]);
        __half2 h1 = __floats2half2_rn(a[2], a[3]);
        uint2 o;
        o.x = *(uint32_t*)&h0; o.y = *(uint32_t*)&h1;
        *(uint2*)(g_Btf + ((size_t)z * OUT_FC + n) * IN_FC + k0) = o;
    }
}

// ---------------- kernel 3: HMMA fp16 GEMM, cp.async double-buffered ----------------
// grid (157, 8), block 256 = 4 m-warps x 2 n-warps. Tile 128x64, K-chunk 32,
// 2-stage cp.async pipeline hides global-load latency under MMA compute.
__global__ void __launch_bounds__(256) gemm_mma_kernel(
    const float* __restrict__ a1, const float* __restrict__ a2)
{
    __shared__ __align__(16) __half sA[2][128 * 32];  // [stage][m][k], SW64 rows
    __shared__ __align__(16) __half sB[2][64 * 32];   // [stage][n][k], SW64 rows
    __shared__ float sP1[128], sP2[128];
    __shared__ float sW1[64], sW2[64];

    int z = blockIdx.y, head = z & 3, dir = z >> 2;
    int m0 = blockIdx.x * 128;
    int tid = threadIdx.x, wid = tid >> 5, lane = tid & 31;
    int wm = wid & 3, wn = wid >> 2;

    if (tid < 128) { sP1[tid] = 0.0f; sP2[tid] = 0.0f; }
    if (tid < 64) {
        int ao = head * 2 * OUT_FC + dir * OUT_FC + tid;
        sW1[tid] = a1[ao];
        sW2[tid] = a2[ao];
    }

    uint32_t bA = smem_u32(sA), bB = smem_u32(sB);

    int arow = tid >> 1, ahalf = tid & 1;
    int am = m0 + arow;
    bool aok = am < N_NODESC;
    int amsafe = aok ? am : 0;
    int azf = aok ? 16 : 0;
    const __half* xf = g_Xf + ((size_t)dir * N_NODESC + amsafe) * IN_FC + ahalf * 16;
    int brow = (tid >> 1) & 63;
    const __half* bf = g_Btf + ((size_t)z * OUT_FC + brow) * IN_FC + ahalf * 16;

    uint32_t aso[2], bso[2];
#pragma unroll
    for (int cg = 0; cg < 2; cg++) {
        aso[cg] = SWZ64((uint32_t)(arow * 64 + ahalf * 32 + cg * 16));
        bso[cg] = SWZ64((uint32_t)(brow * 64 + ahalf * 32 + cg * 16));
    }

    float acc[2][4][4];
#pragma unroll
    for (int t = 0; t < 2; t++)
#pragma unroll
        for (int na = 0; na < 4; na++)
#pragma unroll
            for (int r = 0; r < 4; r++) acc[t][na][r] = 0.0f;

    // prologue: stage chunk 0 into buffer 0
#pragma unroll
    for (int cg = 0; cg < 2; cg++)
        CP_ASYNC_16(bA + aso[cg], xf + cg * 8, azf);
    if (tid < 128)
#pragma unroll
        for (int cg = 0; cg < 2; cg++)
            CP_ASYNC_16(bB + bso[cg], bf + cg * 8, 16);
    CP_COMMIT();

    for (int c = 0; c < 8; c++) {
        int cur = c & 1;
        // stage chunk c+1 into the other buffer
        if (c + 1 < 8) {
            int kc = (c + 1) * 32;
            uint32_t abase = bA + (cur ^ 1) * 8192;
            uint32_t bbase = bB + (cur ^ 1) * 4096;
#pragma unroll
            for (int cg = 0; cg < 2; cg++)
                CP_ASYNC_16(abase + aso[cg], xf + kc + cg * 8, azf);
            if (tid < 128)
#pragma unroll
                for (int cg = 0; cg < 2; cg++)
                    CP_ASYNC_16(bbase + bso[cg], bf + kc + cg * 8, 16);
            CP_COMMIT();
            CP_WAIT1();   // chunk c's group complete; c+1 in flight
        } else {
            CP_WAIT0();
        }
        __syncthreads();

        uint32_t cA = bA + cur * 8192;
        uint32_t cB = bB + cur * 4096;
#pragma unroll
        for (int ks = 0; ks < 2; ks++) {
            int k0 = ks * 16;
            uint32_t af[2][4];
#pragma unroll
            for (int t = 0; t < 2; t++) {
                int rowA = wm * 32 + t * 16 + (lane & 7) + ((lane >> 3) & 1) * 8;
                int kk = k0 + ((lane >> 4) & 1) * 8;
                uint32_t off = SWZ64((uint32_t)(rowA * 64 + kk * 2));
                LDSM_X4(af[t], cA + off);
            }
            uint32_t bfr[2][4];
#pragma unroll
            for (int p = 0; p < 2; p++) {
                int rowB = wn * 32 + p * 16 + (lane & 7) + ((lane >> 4) & 1) * 8;
                int kk = k0 + ((lane >> 3) & 1) * 8;
                uint32_t off = SWZ64((uint32_t)(rowB * 64 + kk * 2));
                LDSM_X4(bfr[p], cB + off);
            }
#pragma unroll
            for (int t = 0; t < 2; t++) {
#pragma unroll
                for (int na = 0; na < 4; na++) {
                    int p = na >> 1, s = (na & 1) * 2;
                    MMA_F16(acc[t][na], af[t], bfr[p][s], bfr[p][s + 1]);
                }
            }
        }
        __syncthreads();   // everyone done reading buf[cur] before it is re-staged
    }

    // epilogue: D fragment -> fp16 rows + projection partials
    int g = lane >> 2, tig = lane & 3;
#pragma unroll
    for (int t = 0; t < 2; t++) {
#pragma unroll
        for (int half = 0; half < 2; half++) {
            int rl = wm * 32 + t * 16 + g + half * 8;
            int m = m0 + rl;
            if (m >= N_NODESC) continue;
            __half* o = &g_STh[(((size_t)dir * N_NODESC + m) * HEADSC + head) * OUT_FC];
            float d1 = 0.f, d2 = 0.f;
#pragma unroll
            for (int na = 0; na < 4; na++) {
                int col = wn * 32 + na * 8 + tig * 2;
                float v0 = acc[t][na][half * 2 + 0];
                float v1 = acc[t][na][half * 2 + 1];
                *(__half2*)&o[col] = __floats2half2_rn(v0, v1);
                d1 += v0 * sW1[col] + v1 * sW1[col + 1];
                d2 += v0 * sW2[col] + v1 * sW2[col + 1];
            }
            atomicAdd(&sP1[rl], d1);
            atomicAdd(&sP2[rl], d2);
        }
    }
    __syncthreads();
    if (tid < 128) {
        int m = m0 + tid;
        if (m < N_NODESC) {
            g_P1[m * 8 + z] = sP1[tid];
            g_P2[m * 8 + z] = sP2[tid];
        }
    }
}

// ---------------- kernel 4: fused softmax-weight + gather aggregation + ELU ------
__global__ void __launch_bounds__(256) agg_kernel(float* __restrict__ out) {
    __shared__ float sAl[8][CAPC * HEADSC];   // per-warp alpha tile: [slot][head]

    int wslot = threadIdx.x >> 5;
    int gw = (blockIdx.x * 256 + threadIdx.x) >> 5;
    int lane = threadIdx.x & 31;
    int node = gw >> 1, dir = gw & 1;
    if (node >= N_NODESC) return;

    int deg;
    const int* __restrict__ nbr;
    const float* __restrict__ P;
    const __half* __restrict__ rows;
    int ooff, poff;
    if (dir == 0) {  // h_st: node=src, weights from P2, gather T rows
        deg = g_degS[node]; nbr = g_nbrS + (node << 6);
        P = g_P2; ooff = 0; poff = 4;
        rows = g_STh + (size_t)N_NODESC * (HEADSC * OUT_FC);
    } else {         // h_ts: node=tgt, weights from P1, gather S rows
        deg = g_degT[node]; nbr = g_nbrT + (node << 6);
        P = g_P1; ooff = 4; poff = 0;
        rows = g_STh;
    }

    // ---- phase 1: alphas ----
    int sh = lane & 3;   // head
    int se = lane >> 2;  // slot within chunk of 8
    float own = __ldg(&P[node * 8 + ooff + sh]);

    float wreg[8];
    float denp = 0.0f;
#pragma unroll
    for (int it = 0; it < 8; it++) {
        int j = it * 8 + se;
        float w = 0.0f;
        if (j < deg) {
            int nb = __ldg(&nbr[j]);
            float e = own + __ldg(&P[nb * 8 + poff + sh]);
            e = fmaxf(e, ALPHAC * e);   // leaky_relu (alpha>0)
            w = __expf(e);
        }
        wreg[it] = w;
        denp += w;
    }
    denp += __shfl_xor_sync(0xFFFFFFFFu, denp, 4);
    denp += __shfl_xor_sync(0xFFFFFFFFu, denp, 8);
    denp += __shfl_xor_sync(0xFFFFFFFFu, denp, 16);
    float inv = (denp > 0.0f) ? (1.0f / denp) : 0.0f;
#pragma unroll
    for (int it = 0; it < 8; it++)
        sAl[wslot][((it * 8 + se) << 2) + sh] = wreg[it] * inv;
    __syncwarp();

    // ---- phase 2: gather + accumulate ----
    int fh = lane >> 3;
    int laneoff = fh * OUT_FC + (lane & 7) * 8;

    float a0 = 0.f, a1v = 0.f, a2v = 0.f, a3 = 0.f;
    float a4 = 0.f, a5 = 0.f, a6 = 0.f, a7 = 0.f;

#pragma unroll 8
    for (int j = 0; j < deg; j++) {
        int nbb = __ldg(&nbr[j]);
        float al = sAl[wslot][(j << 2) + fh];
        const __half* base = rows + nbb * (HEADSC * OUT_FC) + laneoff;
        uint4 q = *(const uint4*)(base);
        float2 v0 = __half22float2(*(const __half2*)&q.x);
        float2 v1 = __half22float2(*(const __half2*)&q.y);
        float2 v2 = __half22float2(*(const __half2*)&q.z);
        float2 v3 = __half22float2(*(const __half2*)&q.w);
        a0 += al * v0.x; a1v += al * v0.y;
        a2v += al * v1.x; a3 += al * v1.y;
        a4 += al * v2.x; a5 += al * v2.y;
        a6 += al * v3.x; a7 += al * v3.y;
    }

    float r0 = (a0 > 0.f) ? a0 : expm1f(a0);
    float r1 = (a1v > 0.f) ? a1v : expm1f(a1v);
    float r2 = (a2v > 0.f) ? a2v : expm1f(a2v);
    float r3 = (a3 > 0.f) ? a3 : expm1f(a3);
    float r4 = (a4 > 0.f) ? a4 : expm1f(a4);
    float r5 = (a5 > 0.f) ? a5 : expm1f(a5);
    float r6 = (a6 > 0.f) ? a6 : expm1f(a6);
    float r7 = (a7 > 0.f) ? a7 : expm1f(a7);

    float* o = out + ((size_t)(dir ? N_NODESC : 0) + node) * (HEADSC * OUT_FC) + laneoff;
    *(float4*)(o)     = make_float4(r0, r1, r2, r3);
    *(float4*)(o + 4) = make_float4(r4, r5, r6, r7);
}

// ---------------- launch ----------------
extern "C" void kernel_launch(void* const* d_in, const int* in_sizes, int n_in,
                              void* d_out, int out_size) {
    const float* x1 = (const float*)d_in[0];
    const float* x2 = (const float*)d_in[1];
    const float* Ws = (const float*)d_in[2];
    const float* Wt = (const float*)d_in[3];
    const float* a1 = (const float*)d_in[4];
    const float* a2 = (const float*)d_in[5];
    const int* tgt  = (const int*)d_in[6];
    const int* src  = (const int*)d_in[7];
    float* out = (float*)d_out;

    // side stream + events for capture-legal fork/join (created on the first,
    // uncaptured, correctness call; reused thereafter — resources, not work)
    static cudaStream_t s2 = nullptr;
    static cudaEvent_t evFork = nullptr, evJoin = nullptr;
    if (s2 == nullptr) {
        cudaStreamCreateWithFlags(&s2, cudaStreamNonBlocking);
        cudaEventCreateWithFlags(&evFork, cudaEventDisableTiming);
        cudaEventCreateWithFlags(&evJoin, cudaEventDisableTiming);
    }

    // fork: CSR chain (zero -> fill) runs concurrently with conv + gemm
    cudaEventRecord(evFork, 0);
    cudaStreamWaitEvent(s2, evFork, 0);
    zero_kernel<<<(N_NODESC + 255) / 256, 256, 0, s2>>>();
    fill_kernel<<<(N_EDGESC + 255) / 256, 256, 0, s2>>>(src, tgt);
    cudaEventRecord(evJoin, s2);

    const int NCONV = 2 * N_NODESC * IN_FC / 8 + 8 * OUT_FC * IN_FC / 4;
    conv_kernel<<<(NCONV + 255) / 256, 256>>>(x1, x2, Ws, Wt);

    dim3 gg((N_NODESC + 127) / 128, 8);
    gemm_mma_kernel<<<gg, 256>>>(a1, a2);

    // join: agg needs both the CSR and the projections/rows
    cudaStreamWaitEvent(0, evJoin, 0);
    agg_kernel<<<(N_NODESC * 2 * 32 + 255) / 256, 256>>>(out);
}